// round 13
// baseline (speedup 1.0000x reference)
#include <cuda_runtime.h>
#include <math_constants.h>

#define T_LEN 8192
#define B_SZ  256
#define E_CH  8
#define KS    15
#define TD    1024
#define TILE_L 2048
#define TPI_F 6.28318530717958647692f

#define PAD(i)   ((i) + ((i) >> 5))
#define F2PAD(i) ((i) + ((i) >> 4))

typedef unsigned long long ull;

// ---- packed f32x2 helpers ----
__device__ __forceinline__ ull pk2(float lo, float hi) {
    ull r;
    asm("mov.b64 %0, {%1, %2};" : "=l"(r) : "f"(lo), "f"(hi));
    return r;
}
__device__ __forceinline__ float2 unpk2(ull v) {
    float lo, hi;
    asm("mov.b64 {%0, %1}, %2;" : "=f"(lo), "=f"(hi) : "l"(v));
    return make_float2(lo, hi);
}
__device__ __forceinline__ ull fma2(ull a, ull b, ull c) {
    ull d;
    asm("fma.rn.f32x2 %0, %1, %2, %3;" : "=l"(d) : "l"(a), "l"(b), "l"(c));
    return d;
}

__device__ __forceinline__ float2 cmulf(float2 a, float2 b) {
    return make_float2(a.x * b.x - a.y * b.y, a.x * b.y + a.y * b.x);
}
__device__ __forceinline__ float2 cadd(float2 a, float2 b) {
    return make_float2(a.x + b.x, a.y + b.y);
}
__device__ __forceinline__ float2 csub(float2 a, float2 b) {
    return make_float2(a.x - b.x, a.y - b.y);
}

// compensated float-float accumulation (TwoSum based)
__device__ __forceinline__ float2 df_add(float2 a, float2 b) {
    float s = a.x + b.x;
    float v = s - a.x;
    float e = (a.x - (s - v)) + (b.x - v);
    e = e + a.y + b.y;
    float hi = s + e;
    return make_float2(hi, e - (hi - s));
}
__device__ __forceinline__ float2 df_addf(float2 a, float b) {
    return df_add(a, make_float2(b, 0.f));
}

// ---------------------------------------------------------------------------
// Kernel A: latent via TILED composed 29-tap dilated conv.
// Tile = 2048 outputs; sx holds [t0-14d, t0+2048+14d) with zero padding, so
// the main loop needs NO per-tap guards. Edge tiles (0,3) add exact
// corrections via guard-free virtual-h (sx zeros provide the padding).
// ~39KB smem + <=85 regs -> 3 blocks/SM (24 warps).
// ---------------------------------------------------------------------------
__global__ __launch_bounds__(256, 3) void latent_kernel(
    const float* __restrict__ x,
    const float* __restrict__ W1, const float* __restrict__ b1,
    const float* __restrict__ W2, const float* __restrict__ b2,
    float* __restrict__ latent)
{
    extern __shared__ float sm[];
    float* sx   = sm;               // PAD(XLmax=5632) -> 5808
    float* sout = sm + 5808;        // PAD(2048) -> 2112
    ull*   hbuf = (ull*)(sm + 7920);// 896 ull = 1792 floats
    float* scw  = sm + 9712;        // 32
    float* sw1  = sm + 9744;        // 32
    float* sw2  = sm + 9776;        // 32

    const int blk  = blockIdx.x;
    const int tile = blk & 3;
    const int be   = blk >> 2;
    const int e    = be & 7;
    const int b    = be >> 3;
    const int d    = 1 << e;
    const int tid  = threadIdx.x;
    const int t0   = tile * TILE_L;
    const int XL   = TILE_L + 28 * d;
    const int xs   = t0 - 14 * d;
    const int hspan = 7 * d;

    const float* xrow = x + (size_t)b * T_LEN;
    for (int i = tid; i < XL; i += 256) {
        int g = xs + i;
        sx[PAD(i)] = ((unsigned)g < (unsigned)T_LEN) ? xrow[g] : 0.f;
    }
    if (tid < 30) {
        sw1[tid] = W1[e * 30 + tid];
        sw2[tid] = W2[e * 30 + tid];
    }
    if (tid >= 32 && tid < 61) {            // composed weights cw_m
        const int m = tid - 32;
        float acc = 0.f;
        const int kmin = (m > 14) ? (m - 14) : 0;
        const int kmax = (m < 14) ? m : 14;
        for (int k = kmin; k <= kmax; k++) {
            acc += W2[e * 30 + k]      * W1[e * 30 + (m - k)]
                 + W2[e * 30 + 15 + k] * W1[e * 30 + 15 + (m - k)];
        }
        scw[m] = acc;
    }
    if (tid == 61) {
        float s2a = 0.f, s2b = 0.f;
        for (int k = 0; k < KS; k++) { s2a += W2[e * 30 + k]; s2b += W2[e * 30 + 15 + k]; }
        scw[29] = b2[e] + s2a * b1[2 * e] + s2b * b1[2 * e + 1];
    }
    __syncthreads();

    // ---- main: composed conv, coset R=8, guard-free taps ----
    {
        float cw[29];
#pragma unroll
        for (int m = 0; m < 29; m++) cw[m] = scw[m];
        const float biasC = scw[29];
        const int cc = tid;                        // 256 chunks x 8 = 2048
        const int p  = cc & (d - 1);
        const int qc = cc >> e;
        const int tb = p + (qc << (e + 3));        // local output base
        float xv[36];
#pragma unroll
        for (int i = 0; i < 36; i++) xv[i] = sx[PAD(tb + i * d)];
#pragma unroll
        for (int rr = 0; rr < 8; rr++) {
            float a0 = biasC, a1 = 0.f;
#pragma unroll
            for (int m = 0; m < 29; m += 2) a0 = fmaf(cw[m], xv[rr + m], a0);
#pragma unroll
            for (int m = 1; m < 29; m += 2) a1 = fmaf(cw[m], xv[rr + m], a1);
            sout[PAD(tb + rr * d)] = a0 + a1;
        }
    }

    // ---- edge tiles: virtual h (guard-free, sx zeros pad) ----
    if (tile == 0) {
        ull w1pk[KS];
#pragma unroll
        for (int j = 0; j < KS; j++) w1pk[j] = pk2(sw1[j], sw1[15 + j]);
        const ull bias1 = pk2(b1[2 * e], b1[2 * e + 1]);
#pragma unroll 1
        for (int i = tid; i < hspan; i += 256) {
            // virtual h at s = i - 7d;  x local idx = i + j*d  (xs = -14d)
            ull a = bias1;
#pragma unroll
            for (int j = 0; j < KS; j++) {
                float v = sx[PAD(i + j * d)];
                a = fma2(w1pk[j], pk2(v, v), a);
            }
            hbuf[i] = a;
        }
    } else if (tile == 3) {
        ull w1pk[KS];
#pragma unroll
        for (int j = 0; j < KS; j++) w1pk[j] = pk2(sw1[j], sw1[15 + j]);
        const ull bias1 = pk2(b1[2 * e], b1[2 * e + 1]);
#pragma unroll 1
        for (int i = tid; i < hspan; i += 256) {
            // virtual h at s = T + i; x local idx = 2048 + i + (j+7)*d
            ull a = bias1;
#pragma unroll
            for (int j = 0; j < KS; j++) {
                float v = sx[PAD(TILE_L + i + (j + 7) * d)];
                a = fma2(w1pk[j], pk2(v, v), a);
            }
            hbuf[i] = a;
        }
    }
    __syncthreads();

    // ---- exact edge corrections ----
    if (tile == 0) {
#pragma unroll 1
        for (int i = tid; i < hspan; i += 256) {
            float corr = 0.f;
#pragma unroll
            for (int k = 0; k < 7; k++) {
                if (i + (k - 7) * d < 0) {
                    float2 h = unpk2(hbuf[i + k * d]);
                    corr += sw2[k] * h.x + sw2[15 + k] * h.y;
                }
            }
            sout[PAD(i)] -= corr;
        }
    } else if (tile == 3) {
#pragma unroll 1
        for (int i = tid; i < hspan; i += 256) {
            float corr = 0.f;
            const int oL = TILE_L - hspan + i;     // local output index
#pragma unroll
            for (int k = 8; k < 15; k++) {
                int idx = i + (k - 14) * d;        // hbuf index = s_k - T
                if (idx >= 0) {
                    float2 h = unpk2(hbuf[idx]);
                    corr += sw2[k] * h.x + sw2[15 + k] * h.y;
                }
            }
            sout[PAD(oL)] -= corr;
        }
    }
    __syncthreads();

    float* lrow = latent + (size_t)be * T_LEN + t0;
    for (int i = tid; i < TILE_L; i += 256) lrow[i] = sout[PAD(i)];
}

// ---------------------------------------------------------------------------
// Kernel B: per-(b,e) row — fc dots, real FFT (8192 real via complex 4096),
// radix-8 Stockham, stage-0 fused with load, stage-3 outputs in registers,
// slim fp32 reductions. (R11 proven version, byte-identical.)
// ---------------------------------------------------------------------------
__global__ __launch_bounds__(512, 2) void fft_kernel(
    const float* __restrict__ latent,
    const float* __restrict__ fcW, const float* __restrict__ fcb,
    float* __restrict__ pOut, float* __restrict__ fOut,
    float* __restrict__ aOut, float* __restrict__ bOut)
{
    const int M = 4096;
    extern __shared__ float smf[];
    float2* bufA = (float2*)smf;
    float2* bufB = bufA + 4352;
    float2* tw   = bufB + 4352;
    __shared__ float red[64];

    const int be = blockIdx.x;
    const int e  = be & 7;
    const int tid = threadIdx.x;
    const float RS = 0.70710678118654752440f;

    const float2* rowc = (const float2*)(latent + (size_t)be * T_LEN);
    const float2* fw0  = (const float2*)(fcW + (size_t)(e * 2 + 0) * T_LEN);
    const float2* fw1  = (const float2*)(fcW + (size_t)(e * 2 + 1) * T_LEN);

    float2 v0 = make_float2(0.f, 0.f), v1 = make_float2(0.f, 0.f);
    float2 z[8];
#pragma unroll
    for (int q = 0; q < 8; q++) {
        const int i = tid + 512 * q;
        float2 zz = rowc[i];
        z[q] = zz;
        float2 a0 = fw0[i], a1 = fw1[i];
        v0 = df_addf(v0, zz.x * a0.x + zz.y * a0.y);
        v1 = df_addf(v1, zz.x * a1.x + zz.y * a1.y);
    }
    {
        float s, c;
        sincosf(-(float)CUDART_PI * (float)tid / 2048.0f, &s, &c);
        tw[tid] = make_float2(c, s);
    }
    {
        float2 t0 = cadd(z[0], z[4]), t1 = csub(z[0], z[4]);
        float2 t2 = cadd(z[2], z[6]), t3 = csub(z[2], z[6]);
        float2 E0 = cadd(t0, t2);
        float2 E1 = make_float2(t1.x + t3.y, t1.y - t3.x);
        float2 E2 = csub(t0, t2);
        float2 E3 = make_float2(t1.x - t3.y, t1.y + t3.x);
        float2 s0 = cadd(z[1], z[5]), s1 = csub(z[1], z[5]);
        float2 s2 = cadd(z[3], z[7]), s3 = csub(z[3], z[7]);
        float2 O0 = cadd(s0, s2);
        float2 O1 = make_float2(s1.x + s3.y, s1.y - s3.x);
        float2 O2 = csub(s0, s2);
        float2 O3 = make_float2(s1.x - s3.y, s1.y + s3.x);
        float2 Q1 = make_float2(RS * (O1.x + O1.y), RS * (O1.y - O1.x));
        float2 Q2 = make_float2(O2.y, -O2.x);
        float2 Q3 = make_float2(RS * (O3.y - O3.x), -RS * (O3.x + O3.y));
        const int ob = tid << 3;
        bufA[F2PAD(ob)]     = cadd(E0, O0);
        bufA[F2PAD(ob + 1)] = cadd(E1, Q1);
        bufA[F2PAD(ob + 2)] = cadd(E2, Q2);
        bufA[F2PAD(ob + 3)] = cadd(E3, Q3);
        bufA[F2PAD(ob + 4)] = csub(E0, O0);
        bufA[F2PAD(ob + 5)] = csub(E1, Q1);
        bufA[F2PAD(ob + 6)] = csub(E2, Q2);
        bufA[F2PAD(ob + 7)] = csub(E3, Q3);
    }
    __syncthreads();

    float2* bin  = bufA;
    float2* bout = bufB;
#pragma unroll
    for (int sg = 1; sg <= 2; sg++) {
        const int m = 1 << (3 * sg);
        const int idx = tid;
        const int r = idx & (m - 1);
        float2 W = tw[r << (9 - 3 * sg)];

        float2 u0 = bin[F2PAD(idx)];
        float2 z1 = bin[F2PAD(idx + 512)];
        float2 z2 = bin[F2PAD(idx + 1024)];
        float2 z3 = bin[F2PAD(idx + 1536)];
        float2 z4 = bin[F2PAD(idx + 2048)];
        float2 z5 = bin[F2PAD(idx + 2560)];
        float2 z6 = bin[F2PAD(idx + 3072)];
        float2 z7 = bin[F2PAD(idx + 3584)];

        float2 W2 = cmulf(W, W);
        float2 W3 = cmulf(W2, W);
        float2 W4 = cmulf(W2, W2);
        float2 W5 = cmulf(W4, W);
        float2 W6 = cmulf(W4, W2);
        float2 W7 = cmulf(W4, W3);

        float2 u1 = cmulf(z1, W);
        float2 u2 = cmulf(z2, W2);
        float2 u3 = cmulf(z3, W3);
        float2 u4 = cmulf(z4, W4);
        float2 u5 = cmulf(z5, W5);
        float2 u6 = cmulf(z6, W6);
        float2 u7 = cmulf(z7, W7);

        float2 t0 = cadd(u0, u4), t1 = csub(u0, u4);
        float2 t2 = cadd(u2, u6), t3 = csub(u2, u6);
        float2 E0 = cadd(t0, t2);
        float2 E1 = make_float2(t1.x + t3.y, t1.y - t3.x);
        float2 E2 = csub(t0, t2);
        float2 E3 = make_float2(t1.x - t3.y, t1.y + t3.x);
        float2 s0 = cadd(u1, u5), s1 = csub(u1, u5);
        float2 s2 = cadd(u3, u7), s3 = csub(u3, u7);
        float2 O0 = cadd(s0, s2);
        float2 O1 = make_float2(s1.x + s3.y, s1.y - s3.x);
        float2 O2 = csub(s0, s2);
        float2 O3 = make_float2(s1.x - s3.y, s1.y + s3.x);
        float2 Q1 = make_float2(RS * (O1.x + O1.y), RS * (O1.y - O1.x));
        float2 Q2 = make_float2(O2.y, -O2.x);
        float2 Q3 = make_float2(RS * (O3.y - O3.x), -RS * (O3.x + O3.y));

        const int ob = ((idx - r) << 3) + r;
        bout[F2PAD(ob)]         = cadd(E0, O0);
        bout[F2PAD(ob + m)]     = cadd(E1, Q1);
        bout[F2PAD(ob + 2 * m)] = cadd(E2, Q2);
        bout[F2PAD(ob + 3 * m)] = cadd(E3, Q3);
        bout[F2PAD(ob + 4 * m)] = csub(E0, O0);
        bout[F2PAD(ob + 5 * m)] = csub(E1, Q1);
        bout[F2PAD(ob + 6 * m)] = csub(E2, Q2);
        bout[F2PAD(ob + 7 * m)] = csub(E3, Q3);
        __syncthreads();
        float2* tmp = bin; bin = bout; bout = tmp;
    }

    {
        const int idx = tid;
        float2 W = tw[idx];

        float2 u0 = bin[F2PAD(idx)];
        float2 z1 = bin[F2PAD(idx + 512)];
        float2 z2 = bin[F2PAD(idx + 1024)];
        float2 z3 = bin[F2PAD(idx + 1536)];
        float2 z4 = bin[F2PAD(idx + 2048)];
        float2 z5 = bin[F2PAD(idx + 2560)];
        float2 z6 = bin[F2PAD(idx + 3072)];
        float2 z7 = bin[F2PAD(idx + 3584)];

        float2 W2 = cmulf(W, W);
        float2 W3 = cmulf(W2, W);
        float2 W4 = cmulf(W2, W2);
        float2 W5 = cmulf(W4, W);
        float2 W6 = cmulf(W4, W2);
        float2 W7 = cmulf(W4, W3);

        float2 u1 = cmulf(z1, W);
        float2 u2 = cmulf(z2, W2);
        float2 u3 = cmulf(z3, W3);
        float2 u4 = cmulf(z4, W4);
        float2 u5 = cmulf(z5, W5);
        float2 u6 = cmulf(z6, W6);
        float2 u7 = cmulf(z7, W7);

        float2 t0 = cadd(u0, u4), t1 = csub(u0, u4);
        float2 t2 = cadd(u2, u6), t3 = csub(u2, u6);
        float2 E0 = cadd(t0, t2);
        float2 E1 = make_float2(t1.x + t3.y, t1.y - t3.x);
        float2 E2 = csub(t0, t2);
        float2 E3 = make_float2(t1.x - t3.y, t1.y + t3.x);
        float2 s0 = cadd(u1, u5), s1 = csub(u1, u5);
        float2 s2 = cadd(u3, u7), s3 = csub(u3, u7);
        float2 O0 = cadd(s0, s2);
        float2 O1 = make_float2(s1.x + s3.y, s1.y - s3.x);
        float2 O2 = csub(s0, s2);
        float2 O3 = make_float2(s1.x - s3.y, s1.y + s3.x);
        float2 Q1 = make_float2(RS * (O1.x + O1.y), RS * (O1.y - O1.x));
        float2 Q2 = make_float2(O2.y, -O2.x);
        float2 Q3 = make_float2(RS * (O3.y - O3.x), -RS * (O3.x + O3.y));

        z[0] = cadd(E0, O0); z[1] = cadd(E1, Q1);
        z[2] = cadd(E2, Q2); z[3] = cadd(E3, Q3);
        z[4] = csub(E0, O0); z[5] = csub(E1, Q1);
        z[6] = csub(E2, Q2); z[7] = csub(E3, Q3);
#pragma unroll
        for (int q = 0; q < 8; q++)
            bout[F2PAD(idx + 512 * q)] = z[q];
    }
    __syncthreads();

    float psum = 0.f, wsum = 0.f;
#pragma unroll
    for (int q = 0; q < 8; q++) {
        const int k = tid + 512 * q;
        if (k > 0) {
            float2 zk = z[q];
            float2 zm = bout[F2PAD(M - k)];
            float Ax = 0.5f * (zk.x + zm.x), Ay = 0.5f * (zk.y - zm.y);
            float Bx = 0.5f * (zk.x - zm.x), By = 0.5f * (zk.y + zm.y);
            float s, c;
            __sincosf(-(float)CUDART_PI * (float)k / (float)M, &s, &c);
            float Xr = Ax + c * By + s * Bx;
            float Xi = Ay - c * Bx + s * By;
            float pw = Xr * Xr + Xi * Xi;
            psum += pw;
            wsum = fmaf((float)k, pw, wsum);
        }
    }
    if (tid == 0) {
        float xm = z[0].x - z[0].y;
        psum += xm * xm;
        wsum = fmaf((float)M, xm * xm, wsum);
    }

    float v0s = v0.x + v0.y;
    float v1s = v1.x + v1.y;

    const unsigned mask = 0xffffffffu;
#pragma unroll
    for (int o = 16; o > 0; o >>= 1) {
        psum += __shfl_down_sync(mask, psum, o);
        wsum += __shfl_down_sync(mask, wsum, o);
        v0s  += __shfl_down_sync(mask, v0s, o);
        v1s  += __shfl_down_sync(mask, v1s, o);
    }
    const int warp = tid >> 5, lane = tid & 31;
    if (lane == 0) {
        red[warp] = psum; red[16 + warp] = wsum;
        red[32 + warp] = v0s; red[48 + warp] = v1s;
    }
    __syncthreads();
    if (tid == 0) {
        double P = 0, Wm = 0, V0 = 0, V1 = 0;
        for (int i = 0; i < 16; i++) {
            P  += (double)red[i];
            Wm += (double)red[16 + i];
            V0 += (double)red[32 + i];
            V1 += (double)red[48 + i];
        }
        V0 += (double)fcb[e * 2];
        V1 += (double)fcb[e * 2 + 1];
        float f    = (float)(0.5 * Wm / P);
        float a    = 2.0f * sqrtf((float)P) / (float)T_LEN;
        float boff = (z[0].x + z[0].y) / (float)T_LEN;
        float p    = atan2f((float)V1, (float)V0) / TPI_F;
        pOut[be] = p; fOut[be] = f; aOut[be] = a; bOut[be] = boff;
    }
}

// ---------------------------------------------------------------------------
// Kernel D: sinusoid resynthesis + ANALYTIC deconv tree. (R9/R11 proven.)
// ---------------------------------------------------------------------------
__global__ __launch_bounds__(256) void sig_tree_kernel(
    const float* __restrict__ pArr, const float* __restrict__ fArr,
    const float* __restrict__ aArr, const float* __restrict__ bArr,
    const float* __restrict__ dW0, const float* __restrict__ db0,
    const float* __restrict__ dW1, const float* __restrict__ db1,
    const float* __restrict__ dW2, const float* __restrict__ db2,
    float* __restrict__ sig, float* __restrict__ outp)
{
    extern __shared__ float smd[];
    const int SW  = TD + 42;
    const int SPW = TD + 8;
    float2* ssig2 = (float2*)smd;
    float*  spart = (float*)(ssig2 + 4 * SW);
    float*  y0e   = spart + 4 * SPW;
    float*  y1e   = y0e + 4 * 36;

    __shared__ float sca[8], scf[8], scp[8], scb[8];
    __shared__ float2 rotv[8];
    __shared__ float sGr[8], sGi[8];
    __shared__ float sC;
    __shared__ ull sdw0p[4 * KS], sdw1p[2 * KS], sdw2p[KS];
    __shared__ float sdb0[4], sdb1[2], sdb2s;

    const int blk  = blockIdx.x;
    const int tile = blk & 7;
    const int b    = blk >> 3;
    const int t0   = tile * TD;
    const int tid  = threadIdx.x;
    const float inv = 2.0f / (float)(T_LEN - 1);

    if (tid < 8) {
        const int e = tid;
        float fv = fArr[b * 8 + e];
        float av = aArr[b * 8 + e];
        sca[e] = av; scf[e] = fv;
        scp[e] = pArr[b * 8 + e]; scb[e] = bArr[b * 8 + e];
        float S, C;
        sincospif(2.0f * fv * inv, &S, &C);
        rotv[e] = make_float2(C, S);

        float h0r = 0.f, h0i = 0.f, h1r = 0.f, h1i = 0.f, h2r = 0.f, h2i = 0.f;
        const int row1 = ((e >> 2) << 1) | ((e >> 1) & 1);
        const int row2 = e >> 2;
#pragma unroll
        for (int k = 0; k < KS; k++) {
            float ph = 2.0f * fv * (float)(k - 7) * inv;
            float ss, cc;
            sincospif(ph, &ss, &cc);
            float w0 = dW0[e * KS + k];
            float w1 = dW1[row1 * KS + k];
            float w2 = dW2[row2 * KS + k];
            h0r += w0 * cc; h0i += w0 * ss;
            h1r += w1 * cc; h1i += w1 * ss;
            h2r += w2 * cc; h2i += w2 * ss;
        }
        float g1r = h0r * h1r - h0i * h1i;
        float g1i = h0r * h1i + h0i * h1r;
        sGr[e] = av * (g1r * h2r - g1i * h2i);
        sGi[e] = av * (g1r * h2i + g1i * h2r);
    }
    if (tid == 8) {
        float S0[8], S1[4], S2[2];
        for (int e2 = 0; e2 < 8; e2++) {
            float s = 0.f;
            for (int k = 0; k < KS; k++) s += dW0[e2 * KS + k];
            S0[e2] = s;
        }
        for (int g = 0; g < 4; g++) {
            float s = 0.f;
            for (int k = 0; k < KS; k++) s += dW1[g * KS + k];
            S1[g] = s;
        }
        for (int q = 0; q < 2; q++) {
            float s = 0.f;
            for (int k = 0; k < KS; k++) s += dW2[q * KS + k];
            S2[q] = s;
        }
        float Cv = db2[0];
        for (int q = 0; q < 2; q++) Cv += S2[q] * db1[q];
        for (int g = 0; g < 4; g++) Cv += S2[g >> 1] * S1[g] * db0[g];
        for (int e2 = 0; e2 < 8; e2++)
            Cv += S2[e2 >> 2] * S1[e2 >> 1] * S0[e2] * bArr[b * 8 + e2];
        sC = Cv;
    }
    if (tid < 4 * KS) {
        int g = tid / KS, k = tid - g * KS;
        sdw0p[tid] = pk2(dW0[(2 * g) * KS + k], dW0[(2 * g + 1) * KS + k]);
    }
    if (tid < 2 * KS) {
        int g = tid / KS, k = tid - g * KS;
        sdw1p[tid] = pk2(dW1[(2 * g) * KS + k], dW1[(2 * g + 1) * KS + k]);
    }
    if (tid < KS) sdw2p[tid] = pk2(dW2[tid], dW2[KS + tid]);
    if (tid < 4) sdb0[tid] = db0[tid];
    if (tid < 2) sdb1[tid] = db1[tid];
    if (tid == 0) sdb2s = db2[0];
    __syncthreads();

    {
        const int pr  = tid >> 6;
        const int sub = tid & 63;
        const int j0  = sub * 17;
        const int ts  = t0 - 21 + j0;
        const int e0 = 2 * pr, e1 = 2 * pr + 1;
        const float arg0 = -1.0f + (float)ts * inv;
        float s0, c0, s1, c1;
        sincospif(2.0f * (scf[e0] * arg0 + scp[e0]), &s0, &c0);
        sincospif(2.0f * (scf[e1] * arg0 + scp[e1]), &s1, &c1);
        const float2 r0 = rotv[e0], r1 = rotv[e1];
        const float a0 = sca[e0], b0 = scb[e0];
        const float a1 = sca[e1], b1v = scb[e1];
        const float gr0 = sGr[e0], gi0 = sGi[e0];
        const float gr1 = sGr[e1], gi1 = sGi[e1];
        float* sprow = spart + pr * SPW;
#pragma unroll
        for (int jj = 0; jj < 17; jj++) {
            int j = j0 + jj;
            int t = ts + jj;
            if (j < SW) {
                bool ok = ((unsigned)t < (unsigned)T_LEN);
                float v0 = ok ? (a0 * s0 + b0)  : 0.f;
                float v1 = ok ? (a1 * s1 + b1v) : 0.f;
                ssig2[pr * SW + j] = make_float2(v0, v1);
                if (j >= 21 && j < 21 + TD)
                    sprow[j - 21] = gr0 * s0 + gi0 * c0 + gr1 * s1 + gi1 * c1;
            }
            float ns0 = s0 * r0.x + c0 * r0.y;
            c0 = c0 * r0.x - s0 * r0.y; s0 = ns0;
            float ns1 = s1 * r1.x + c1 * r1.y;
            c1 = c1 * r1.x - s1 * r1.y; s1 = ns1;
        }
    }
    __syncthreads();

    for (int i = tid; i < 8 * TD; i += 256) {
        int e = i >> 10, jj = i & (TD - 1);
        float2 v = ssig2[(e >> 1) * SW + 21 + jj];
        sig[((size_t)b * 8 + e) * T_LEN + t0 + jj] = (e & 1) ? v.y : v.x;
    }

    {
        const float Cv = sC;
        const bool left  = (tile == 0);
        const bool right = (tile == 7);
        float* orow = outp + (size_t)b * T_LEN + t0;
#pragma unroll
        for (int jj = tid; jj < TD; jj += 256) {
            bool skip = (left && jj < 21) || (right && jj >= TD - 21);
            if (!skip) {
                orow[jj] = spart[jj] + spart[SPW + jj] +
                           spart[2 * SPW + jj] + spart[3 * SPW + jj] + Cv;
            }
        }
    }

    {
        const bool left  = (tile == 0);
        const bool right = (tile == 7);
        const bool edge  = left || right;

        if (edge && tid < 140) {
            const int g = tid / 35, j = tid - g * 35;
            float acc = sdb0[g];
#pragma unroll
            for (int k = 0; k < KS; k++) {
                int tG = (left ? j : (T_LEN - 35 + j)) + k - 7;
                int slot = tG - t0 + 21;
                float2 w = unpk2(sdw0p[g * KS + k]);
                float2 sv = ssig2[g * SW + slot];
                acc += w.x * sv.x + w.y * sv.y;
            }
            y0e[g * 36 + j] = acc;
        }
        __syncthreads();

        if (edge && tid < 56) {
            const int g1 = tid / 28, j = tid - g1 * 28;
            float acc = sdb1[g1];
#pragma unroll
            for (int k = 0; k < KS; k++) {
                int idx; bool ok;
                if (left) { idx = j + k - 7; ok = (idx >= 0); }
                else      { idx = j + k;     ok = (idx < 35); }
                if (ok) {
                    float2 w = unpk2(sdw1p[g1 * KS + k]);
                    acc += w.x * y0e[(2 * g1) * 36 + idx]
                         + w.y * y0e[(2 * g1 + 1) * 36 + idx];
                }
            }
            y1e[g1 * 28 + j] = acc;
        }
        __syncthreads();

        if (edge && tid < 21) {
            float acc = sdb2s;
#pragma unroll
            for (int k = 0; k < KS; k++) {
                int idx; bool ok;
                if (left) { idx = tid + k - 7; ok = (idx >= 0); }
                else      { idx = tid + k;     ok = (idx < 28); }
                if (ok) {
                    float2 w = unpk2(sdw2p[k]);
                    acc += w.x * y1e[idx] + w.y * y1e[28 + idx];
                }
            }
            int tG = left ? tid : (T_LEN - 21 + tid);
            outp[(size_t)b * T_LEN + tG] = acc;
        }
    }
}

// ---------------------------------------------------------------------------
extern "C" void kernel_launch(void* const* d_in, const int* in_sizes, int n_in,
                              void* d_out, int out_size)
{
    const float* x   = (const float*)d_in[0];
    const float* W1  = (const float*)d_in[1];
    const float* b1  = (const float*)d_in[2];
    const float* W2  = (const float*)d_in[3];
    const float* b2  = (const float*)d_in[4];
    const float* fcW = (const float*)d_in[5];
    const float* fcb = (const float*)d_in[6];
    const float* dW0 = (const float*)d_in[7];
    const float* db0 = (const float*)d_in[8];
    const float* dW1 = (const float*)d_in[9];
    const float* db1 = (const float*)d_in[10];
    const float* dW2 = (const float*)d_in[11];
    const float* db2 = (const float*)d_in[12];

    float* out = (float*)d_out;
    float* outMain = out;                                        // (B, T)
    float* latent  = out + (size_t)B_SZ * T_LEN;                 // (B, E, T)
    float* sig     = latent + (size_t)B_SZ * E_CH * T_LEN;       // (B, E, T)
    float* pOut    = sig + (size_t)B_SZ * E_CH * T_LEN;          // (B, E, 1)
    float* fOut    = pOut + B_SZ * E_CH;
    float* aOut    = fOut + B_SZ * E_CH;
    float* bOut    = aOut + B_SZ * E_CH;

    const size_t smA = (size_t)9808 * sizeof(float);             // ~39KB
    const size_t smB = (size_t)(4352 * 2 + 512) * sizeof(float2);
    const size_t smD = (size_t)(4 * (TD + 42)) * sizeof(float2)
                     + (size_t)(4 * (TD + 8) + 4 * 36 + 2 * 28) * sizeof(float);

    cudaFuncSetAttribute(latent_kernel,   cudaFuncAttributeMaxDynamicSharedMemorySize, (int)smA);
    cudaFuncSetAttribute(fft_kernel,      cudaFuncAttributeMaxDynamicSharedMemorySize, (int)smB);
    cudaFuncSetAttribute(sig_tree_kernel, cudaFuncAttributeMaxDynamicSharedMemorySize, (int)smD);

    latent_kernel<<<B_SZ * E_CH * 4, 256, smA>>>(x, W1, b1, W2, b2, latent);
    fft_kernel<<<B_SZ * E_CH, 512, smB>>>(latent, fcW, fcb, pOut, fOut, aOut, bOut);
    sig_tree_kernel<<<B_SZ * (T_LEN / TD), 256, smD>>>(pOut, fOut, aOut, bOut,
                                                       dW0, db0, dW1, db1, dW2, db2,
                                                       sig, outMain);
}

// round 14
// speedup vs baseline: 1.0099x; 1.0099x over previous
#include <cuda_runtime.h>
#include <math_constants.h>

#define T_LEN 8192
#define B_SZ  256
#define E_CH  8
#define KS    15
#define TD    1024
#define HOFF  1792
#define TPI_F 6.28318530717958647692f

#define PAD(i)   ((i) + ((i) >> 5))
#define F2PAD(i) ((i) + ((i) >> 4))

typedef unsigned long long ull;

// ---- packed f32x2 helpers ----
__device__ __forceinline__ ull pk2(float lo, float hi) {
    ull r;
    asm("mov.b64 %0, {%1, %2};" : "=l"(r) : "f"(lo), "f"(hi));
    return r;
}
__device__ __forceinline__ float2 unpk2(ull v) {
    float lo, hi;
    asm("mov.b64 {%0, %1}, %2;" : "=f"(lo), "=f"(hi) : "l"(v));
    return make_float2(lo, hi);
}
__device__ __forceinline__ ull fma2(ull a, ull b, ull c) {
    ull d;
    asm("fma.rn.f32x2 %0, %1, %2, %3;" : "=l"(d) : "l"(a), "l"(b), "l"(c));
    return d;
}

__device__ __forceinline__ float2 cmulf(float2 a, float2 b) {
    return make_float2(a.x * b.x - a.y * b.y, a.x * b.y + a.y * b.x);
}
__device__ __forceinline__ float2 cadd(float2 a, float2 b) {
    return make_float2(a.x + b.x, a.y + b.y);
}
__device__ __forceinline__ float2 csub(float2 a, float2 b) {
    return make_float2(a.x - b.x, a.y - b.y);
}

// compensated float-float accumulation (TwoSum based)
__device__ __forceinline__ float2 df_add(float2 a, float2 b) {
    float s = a.x + b.x;
    float v = s - a.x;
    float e = (a.x - (s - v)) + (b.x - v);
    e = e + a.y + b.y;
    float hi = s + e;
    return make_float2(hi, e - (hi - s));
}
__device__ __forceinline__ float2 df_addf(float2 a, float b) {
    return df_add(a, make_float2(b, 0.f));
}

// ---------------------------------------------------------------------------
// Fused kernel: composed-conv latent (guard-free, zero-padded halo) +
// exact edge corrections + latent writeback + fc dots + radix-8 FFT +
// spectral reductions. One block per (b,e) row.
//
// smem (floats):
//   [0, 12144)       sx  (11776 raw, PAD) — DEAD after corrections; bufB aliases it
//   [12144, 20848)   bufA (4352 float2)
//   [20848, 21872)   tw   (512 float2)
//   [21872, 25456)   hbuf (1792 ull: hL[0..896), hR[896..1792))
// ---------------------------------------------------------------------------
__global__ __launch_bounds__(512, 2) void latfft_kernel(
    const float* __restrict__ x,
    const float* __restrict__ W1, const float* __restrict__ b1,
    const float* __restrict__ W2, const float* __restrict__ b2,
    const float* __restrict__ fcW, const float* __restrict__ fcb,
    float* __restrict__ latent,
    float* __restrict__ pOut, float* __restrict__ fOut,
    float* __restrict__ aOut, float* __restrict__ bOut)
{
    const int M = 4096;
    extern __shared__ float sm[];
    float*  sx   = sm;
    float2* bufB = (float2*)sm;                 // aliases sx (dead after conv)
    float2* bufA = (float2*)(sm + 12144);
    float*  bufAf = sm + 12144;                 // float view of bufA
    float2* tw   = (float2*)(sm + 20848);
    ull*    hbuf = (ull*)(sm + 21872);
    __shared__ float red[64];
    __shared__ float sw1s[32], sw2s[32], scw[32];

    const int be = blockIdx.x;
    const int e  = be & 7;
    const int b  = be >> 3;
    const int d  = 1 << e;
    const int tid = threadIdx.x;
    const int hspan = 7 * d;
    const float RS = 0.70710678118654752440f;

    // ---- load x row with zeroed halos ----
    const float* xrow = x + (size_t)b * T_LEN;
    for (int i = tid; i < 11776; i += 512) {
        int g = i - HOFF;
        sx[PAD(i)] = ((unsigned)g < (unsigned)T_LEN) ? xrow[g] : 0.f;
    }
    if (tid < 30) {
        sw1s[tid] = W1[e * 30 + tid];
        sw2s[tid] = W2[e * 30 + tid];
    }
    if (tid >= 32 && tid < 61) {            // composed weights cw_m
        const int m = tid - 32;
        float acc = 0.f;
        const int kmin = (m > 14) ? (m - 14) : 0;
        const int kmax = (m < 14) ? m : 14;
        for (int k = kmin; k <= kmax; k++) {
            acc += W2[e * 30 + k]      * W1[e * 30 + (m - k)]
                 + W2[e * 30 + 15 + k] * W1[e * 30 + 15 + (m - k)];
        }
        scw[m] = acc;
    }
    if (tid == 61) {
        float s2a = 0.f, s2b = 0.f;
        for (int k = 0; k < KS; k++) { s2a += W2[e * 30 + k]; s2b += W2[e * 30 + 15 + k]; }
        scw[29] = b2[e] + s2a * b1[2 * e] + s2b * b1[2 * e + 1];
    }
    {
        float s, c;
        sincosf(-(float)CUDART_PI * (float)tid / 2048.0f, &s, &c);
        tw[tid] = make_float2(c, s);
    }
    __syncthreads();

    // ---- composed 29-tap conv, guard-free, coset R=8, 2 iterations ----
#pragma unroll 1
    for (int it = 0; it < 2; it++) {
        const int cc = it * 512 + tid;
        const int p  = cc & (d - 1);
        const int qc = cc >> e;
        const int tb = p + (qc << (e + 3));
        float xv[36];
#pragma unroll
        for (int i = 0; i < 36; i++)
            xv[i] = sx[PAD(HOFF + tb + (i - 14) * d)];
        float acc[8];
        const float biasC = scw[29];
#pragma unroll
        for (int rr = 0; rr < 8; rr++) acc[rr] = biasC;
#pragma unroll
        for (int m = 0; m < 29; m++) {
            const float w = scw[m];
#pragma unroll
            for (int rr = 0; rr < 8; rr++)
                acc[rr] = fmaf(w, xv[rr + m], acc[rr]);
        }
#pragma unroll
        for (int rr = 0; rr < 8; rr++) {
            const int t = tb + rr * d;
            bufAf[F2PAD(t >> 1) * 2 + (t & 1)] = acc[rr];
        }
    }

    // ---- virtual h at out-of-range positions (guard-free: halo zeros) ----
    {
        ull w1pk[KS];
#pragma unroll
        for (int j = 0; j < KS; j++) w1pk[j] = pk2(sw1s[j], sw1s[15 + j]);
        const ull bias1 = pk2(b1[2 * e], b1[2 * e + 1]);
#pragma unroll 1
        for (int i = tid; i < hspan; i += 512) {
            // left: h(s = i - 7d): taps sx[HOFF + i + (j-14)d]
            ull aL = bias1;
#pragma unroll
            for (int j = 0; j < KS; j++) {
                float v = sx[PAD(HOFF + i + (j - 14) * d)];
                aL = fma2(w1pk[j], pk2(v, v), aL);
            }
            hbuf[i] = aL;
            // right: h(s = T + i): taps sx[HOFF + T + i + (j-7)d]
            ull aR = bias1;
#pragma unroll
            for (int j = 0; j < KS; j++) {
                float v = sx[PAD(HOFF + T_LEN + i + (j - 7) * d)];
                aR = fma2(w1pk[j], pk2(v, v), aR);
            }
            hbuf[896 + i] = aR;
        }
    }
    __syncthreads();

    // ---- exact edge corrections on bufA ----
#pragma unroll 1
    for (int i = tid; i < hspan; i += 512) {
        float corr = 0.f;
#pragma unroll
        for (int k = 0; k < 7; k++) {
            if (i + (k - 7) * d < 0) {
                float2 h = unpk2(hbuf[i + k * d]);
                corr += sw2s[k] * h.x + sw2s[15 + k] * h.y;
            }
        }
        bufAf[F2PAD(i >> 1) * 2 + (i & 1)] -= corr;

        float corr2 = 0.f;
        const int tR = T_LEN - hspan + i;
#pragma unroll
        for (int k = 8; k < 15; k++) {
            int idx = i + (k - 14) * d;       // = s_k - T
            if (idx >= 0) {
                float2 h = unpk2(hbuf[896 + idx]);
                corr2 += sw2s[k] * h.x + sw2s[15 + k] * h.y;
            }
        }
        bufAf[F2PAD(tR >> 1) * 2 + (tR & 1)] -= corr2;
    }
    __syncthreads();

    // ---- writeback latent + fc dots; z[q] regs become FFT stage-0 input ----
    const float2* fw0 = (const float2*)(fcW + (size_t)(e * 2 + 0) * T_LEN);
    const float2* fw1 = (const float2*)(fcW + (size_t)(e * 2 + 1) * T_LEN);
    float2* lrow2 = (float2*)(latent + (size_t)be * T_LEN);
    float2 v0 = make_float2(0.f, 0.f), v1 = make_float2(0.f, 0.f);
    float2 z[8];
#pragma unroll
    for (int q = 0; q < 8; q++) {
        const int i = tid + 512 * q;
        float2 lz = bufA[F2PAD(i)];
        z[q] = lz;
        lrow2[i] = lz;
        float2 a0 = fw0[i], a1 = fw1[i];
        v0 = df_addf(v0, lz.x * a0.x + lz.y * a0.y);
        v1 = df_addf(v1, lz.x * a1.x + lz.y * a1.y);
    }
    __syncthreads();      // all z reads done before stage-0 writes to bufB(=sx)

    // ---- FFT stage 0 (twiddles unity): regs -> bufB ----
    {
        float2 t0 = cadd(z[0], z[4]), t1 = csub(z[0], z[4]);
        float2 t2 = cadd(z[2], z[6]), t3 = csub(z[2], z[6]);
        float2 E0 = cadd(t0, t2);
        float2 E1 = make_float2(t1.x + t3.y, t1.y - t3.x);
        float2 E2 = csub(t0, t2);
        float2 E3 = make_float2(t1.x - t3.y, t1.y + t3.x);
        float2 s0 = cadd(z[1], z[5]), s1 = csub(z[1], z[5]);
        float2 s2 = cadd(z[3], z[7]), s3 = csub(z[3], z[7]);
        float2 O0 = cadd(s0, s2);
        float2 O1 = make_float2(s1.x + s3.y, s1.y - s3.x);
        float2 O2 = csub(s0, s2);
        float2 O3 = make_float2(s1.x - s3.y, s1.y + s3.x);
        float2 Q1 = make_float2(RS * (O1.x + O1.y), RS * (O1.y - O1.x));
        float2 Q2 = make_float2(O2.y, -O2.x);
        float2 Q3 = make_float2(RS * (O3.y - O3.x), -RS * (O3.x + O3.y));
        const int ob = tid << 3;
        bufB[F2PAD(ob)]     = cadd(E0, O0);
        bufB[F2PAD(ob + 1)] = cadd(E1, Q1);
        bufB[F2PAD(ob + 2)] = cadd(E2, Q2);
        bufB[F2PAD(ob + 3)] = cadd(E3, Q3);
        bufB[F2PAD(ob + 4)] = csub(E0, O0);
        bufB[F2PAD(ob + 5)] = csub(E1, Q1);
        bufB[F2PAD(ob + 6)] = csub(E2, Q2);
        bufB[F2PAD(ob + 7)] = csub(E3, Q3);
    }
    __syncthreads();

    // ---- stages 1,2: bufB -> bufA -> bufB ----
    float2* bin  = bufB;
    float2* bout = bufA;
#pragma unroll
    for (int sg = 1; sg <= 2; sg++) {
        const int m = 1 << (3 * sg);
        const int idx = tid;
        const int r = idx & (m - 1);
        float2 W = tw[r << (9 - 3 * sg)];

        float2 u0 = bin[F2PAD(idx)];
        float2 z1 = bin[F2PAD(idx + 512)];
        float2 z2 = bin[F2PAD(idx + 1024)];
        float2 z3 = bin[F2PAD(idx + 1536)];
        float2 z4 = bin[F2PAD(idx + 2048)];
        float2 z5 = bin[F2PAD(idx + 2560)];
        float2 z6 = bin[F2PAD(idx + 3072)];
        float2 z7 = bin[F2PAD(idx + 3584)];

        float2 W2 = cmulf(W, W);
        float2 W3 = cmulf(W2, W);
        float2 W4 = cmulf(W2, W2);
        float2 W5 = cmulf(W4, W);
        float2 W6 = cmulf(W4, W2);
        float2 W7 = cmulf(W4, W3);

        float2 u1 = cmulf(z1, W);
        float2 u2 = cmulf(z2, W2);
        float2 u3 = cmulf(z3, W3);
        float2 u4 = cmulf(z4, W4);
        float2 u5 = cmulf(z5, W5);
        float2 u6 = cmulf(z6, W6);
        float2 u7 = cmulf(z7, W7);

        float2 t0 = cadd(u0, u4), t1 = csub(u0, u4);
        float2 t2 = cadd(u2, u6), t3 = csub(u2, u6);
        float2 E0 = cadd(t0, t2);
        float2 E1 = make_float2(t1.x + t3.y, t1.y - t3.x);
        float2 E2 = csub(t0, t2);
        float2 E3 = make_float2(t1.x - t3.y, t1.y + t3.x);
        float2 s0 = cadd(u1, u5), s1 = csub(u1, u5);
        float2 s2 = cadd(u3, u7), s3 = csub(u3, u7);
        float2 O0 = cadd(s0, s2);
        float2 O1 = make_float2(s1.x + s3.y, s1.y - s3.x);
        float2 O2 = csub(s0, s2);
        float2 O3 = make_float2(s1.x - s3.y, s1.y + s3.x);
        float2 Q1 = make_float2(RS * (O1.x + O1.y), RS * (O1.y - O1.x));
        float2 Q2 = make_float2(O2.y, -O2.x);
        float2 Q3 = make_float2(RS * (O3.y - O3.x), -RS * (O3.x + O3.y));

        const int ob = ((idx - r) << 3) + r;
        bout[F2PAD(ob)]         = cadd(E0, O0);
        bout[F2PAD(ob + m)]     = cadd(E1, Q1);
        bout[F2PAD(ob + 2 * m)] = cadd(E2, Q2);
        bout[F2PAD(ob + 3 * m)] = cadd(E3, Q3);
        bout[F2PAD(ob + 4 * m)] = csub(E0, O0);
        bout[F2PAD(ob + 5 * m)] = csub(E1, Q1);
        bout[F2PAD(ob + 6 * m)] = csub(E2, Q2);
        bout[F2PAD(ob + 7 * m)] = csub(E3, Q3);
        __syncthreads();
        float2* tmp = bin; bin = bout; bout = tmp;
    }
    // bin = bufB holds stage-2 output

    // ---- stage 3: natural-order outputs in regs, staged to bufA ----
    {
        const int idx = tid;
        float2 W = tw[idx];

        float2 u0 = bin[F2PAD(idx)];
        float2 z1 = bin[F2PAD(idx + 512)];
        float2 z2 = bin[F2PAD(idx + 1024)];
        float2 z3 = bin[F2PAD(idx + 1536)];
        float2 z4 = bin[F2PAD(idx + 2048)];
        float2 z5 = bin[F2PAD(idx + 2560)];
        float2 z6 = bin[F2PAD(idx + 3072)];
        float2 z7 = bin[F2PAD(idx + 3584)];

        float2 W2 = cmulf(W, W);
        float2 W3 = cmulf(W2, W);
        float2 W4 = cmulf(W2, W2);
        float2 W5 = cmulf(W4, W);
        float2 W6 = cmulf(W4, W2);
        float2 W7 = cmulf(W4, W3);

        float2 u1 = cmulf(z1, W);
        float2 u2 = cmulf(z2, W2);
        float2 u3 = cmulf(z3, W3);
        float2 u4 = cmulf(z4, W4);
        float2 u5 = cmulf(z5, W5);
        float2 u6 = cmulf(z6, W6);
        float2 u7 = cmulf(z7, W7);

        float2 t0 = cadd(u0, u4), t1 = csub(u0, u4);
        float2 t2 = cadd(u2, u6), t3 = csub(u2, u6);
        float2 E0 = cadd(t0, t2);
        float2 E1 = make_float2(t1.x + t3.y, t1.y - t3.x);
        float2 E2 = csub(t0, t2);
        float2 E3 = make_float2(t1.x - t3.y, t1.y + t3.x);
        float2 s0 = cadd(u1, u5), s1 = csub(u1, u5);
        float2 s2 = cadd(u3, u7), s3 = csub(u3, u7);
        float2 O0 = cadd(s0, s2);
        float2 O1 = make_float2(s1.x + s3.y, s1.y - s3.x);
        float2 O2 = csub(s0, s2);
        float2 O3 = make_float2(s1.x - s3.y, s1.y + s3.x);
        float2 Q1 = make_float2(RS * (O1.x + O1.y), RS * (O1.y - O1.x));
        float2 Q2 = make_float2(O2.y, -O2.x);
        float2 Q3 = make_float2(RS * (O3.y - O3.x), -RS * (O3.x + O3.y));

        z[0] = cadd(E0, O0); z[1] = cadd(E1, Q1);
        z[2] = cadd(E2, Q2); z[3] = cadd(E3, Q3);
        z[4] = csub(E0, O0); z[5] = csub(E1, Q1);
        z[6] = csub(E2, Q2); z[7] = csub(E3, Q3);
#pragma unroll
        for (int q = 0; q < 8; q++)
            bufA[F2PAD(idx + 512 * q)] = z[q];
    }
    __syncthreads();
    // bufA holds Z_k natural order; thread tid holds z[q] = Z_{tid+512q}

    // ---- reduction: plain fp32 partials + pairwise shuffle tree ----
    float psum = 0.f, wsum = 0.f;
#pragma unroll
    for (int q = 0; q < 8; q++) {
        const int k = tid + 512 * q;
        if (k > 0) {
            float2 zk = z[q];
            float2 zm = bufA[F2PAD(M - k)];
            float Ax = 0.5f * (zk.x + zm.x), Ay = 0.5f * (zk.y - zm.y);
            float Bx = 0.5f * (zk.x - zm.x), By = 0.5f * (zk.y + zm.y);
            float s, c;
            __sincosf(-(float)CUDART_PI * (float)k / (float)M, &s, &c);
            float Xr = Ax + c * By + s * Bx;
            float Xi = Ay - c * Bx + s * By;
            float pw = Xr * Xr + Xi * Xi;
            psum += pw;
            wsum = fmaf((float)k, pw, wsum);
        }
    }
    if (tid == 0) {
        float xm = z[0].x - z[0].y;
        psum += xm * xm;
        wsum = fmaf((float)M, xm * xm, wsum);
    }

    float v0s = v0.x + v0.y;
    float v1s = v1.x + v1.y;

    const unsigned mask = 0xffffffffu;
#pragma unroll
    for (int o = 16; o > 0; o >>= 1) {
        psum += __shfl_down_sync(mask, psum, o);
        wsum += __shfl_down_sync(mask, wsum, o);
        v0s  += __shfl_down_sync(mask, v0s, o);
        v1s  += __shfl_down_sync(mask, v1s, o);
    }
    const int warp = tid >> 5, lane = tid & 31;
    if (lane == 0) {
        red[warp] = psum; red[16 + warp] = wsum;
        red[32 + warp] = v0s; red[48 + warp] = v1s;
    }
    __syncthreads();
    if (tid == 0) {
        double P = 0, Wm = 0, V0 = 0, V1 = 0;
        for (int i = 0; i < 16; i++) {
            P  += (double)red[i];
            Wm += (double)red[16 + i];
            V0 += (double)red[32 + i];
            V1 += (double)red[48 + i];
        }
        V0 += (double)fcb[e * 2];
        V1 += (double)fcb[e * 2 + 1];
        float f    = (float)(0.5 * Wm / P);
        float a    = 2.0f * sqrtf((float)P) / (float)T_LEN;
        float boff = (z[0].x + z[0].y) / (float)T_LEN;
        float p    = atan2f((float)V1, (float)V0) / TPI_F;
        pOut[be] = p; fOut[be] = f; aOut[be] = a; bOut[be] = boff;
    }
}

// ---------------------------------------------------------------------------
// Kernel D: sinusoid resynthesis + ANALYTIC deconv tree. (R9/R11 proven.)
// ---------------------------------------------------------------------------
__global__ __launch_bounds__(256) void sig_tree_kernel(
    const float* __restrict__ pArr, const float* __restrict__ fArr,
    const float* __restrict__ aArr, const float* __restrict__ bArr,
    const float* __restrict__ dW0, const float* __restrict__ db0,
    const float* __restrict__ dW1, const float* __restrict__ db1,
    const float* __restrict__ dW2, const float* __restrict__ db2,
    float* __restrict__ sig, float* __restrict__ outp)
{
    extern __shared__ float smd[];
    const int SW  = TD + 42;
    const int SPW = TD + 8;
    float2* ssig2 = (float2*)smd;
    float*  spart = (float*)(ssig2 + 4 * SW);
    float*  y0e   = spart + 4 * SPW;
    float*  y1e   = y0e + 4 * 36;

    __shared__ float sca[8], scf[8], scp[8], scb[8];
    __shared__ float2 rotv[8];
    __shared__ float sGr[8], sGi[8];
    __shared__ float sC;
    __shared__ ull sdw0p[4 * KS], sdw1p[2 * KS], sdw2p[KS];
    __shared__ float sdb0[4], sdb1[2], sdb2s;

    const int blk  = blockIdx.x;
    const int tile = blk & 7;
    const int b    = blk >> 3;
    const int t0   = tile * TD;
    const int tid  = threadIdx.x;
    const float inv = 2.0f / (float)(T_LEN - 1);

    if (tid < 8) {
        const int e = tid;
        float fv = fArr[b * 8 + e];
        float av = aArr[b * 8 + e];
        sca[e] = av; scf[e] = fv;
        scp[e] = pArr[b * 8 + e]; scb[e] = bArr[b * 8 + e];
        float S, C;
        sincospif(2.0f * fv * inv, &S, &C);
        rotv[e] = make_float2(C, S);

        float h0r = 0.f, h0i = 0.f, h1r = 0.f, h1i = 0.f, h2r = 0.f, h2i = 0.f;
        const int row1 = ((e >> 2) << 1) | ((e >> 1) & 1);
        const int row2 = e >> 2;
#pragma unroll
        for (int k = 0; k < KS; k++) {
            float ph = 2.0f * fv * (float)(k - 7) * inv;
            float ss, cc;
            sincospif(ph, &ss, &cc);
            float w0 = dW0[e * KS + k];
            float w1 = dW1[row1 * KS + k];
            float w2 = dW2[row2 * KS + k];
            h0r += w0 * cc; h0i += w0 * ss;
            h1r += w1 * cc; h1i += w1 * ss;
            h2r += w2 * cc; h2i += w2 * ss;
        }
        float g1r = h0r * h1r - h0i * h1i;
        float g1i = h0r * h1i + h0i * h1r;
        sGr[e] = av * (g1r * h2r - g1i * h2i);
        sGi[e] = av * (g1r * h2i + g1i * h2r);
    }
    if (tid == 8) {
        float S0[8], S1[4], S2[2];
        for (int e2 = 0; e2 < 8; e2++) {
            float s = 0.f;
            for (int k = 0; k < KS; k++) s += dW0[e2 * KS + k];
            S0[e2] = s;
        }
        for (int g = 0; g < 4; g++) {
            float s = 0.f;
            for (int k = 0; k < KS; k++) s += dW1[g * KS + k];
            S1[g] = s;
        }
        for (int q = 0; q < 2; q++) {
            float s = 0.f;
            for (int k = 0; k < KS; k++) s += dW2[q * KS + k];
            S2[q] = s;
        }
        float Cv = db2[0];
        for (int q = 0; q < 2; q++) Cv += S2[q] * db1[q];
        for (int g = 0; g < 4; g++) Cv += S2[g >> 1] * S1[g] * db0[g];
        for (int e2 = 0; e2 < 8; e2++)
            Cv += S2[e2 >> 2] * S1[e2 >> 1] * S0[e2] * bArr[b * 8 + e2];
        sC = Cv;
    }
    if (tid < 4 * KS) {
        int g = tid / KS, k = tid - g * KS;
        sdw0p[tid] = pk2(dW0[(2 * g) * KS + k], dW0[(2 * g + 1) * KS + k]);
    }
    if (tid < 2 * KS) {
        int g = tid / KS, k = tid - g * KS;
        sdw1p[tid] = pk2(dW1[(2 * g) * KS + k], dW1[(2 * g + 1) * KS + k]);
    }
    if (tid < KS) sdw2p[tid] = pk2(dW2[tid], dW2[KS + tid]);
    if (tid < 4) sdb0[tid] = db0[tid];
    if (tid < 2) sdb1[tid] = db1[tid];
    if (tid == 0) sdb2s = db2[0];
    __syncthreads();

    {
        const int pr  = tid >> 6;
        const int sub = tid & 63;
        const int j0  = sub * 17;
        const int ts  = t0 - 21 + j0;
        const int e0 = 2 * pr, e1 = 2 * pr + 1;
        const float arg0 = -1.0f + (float)ts * inv;
        float s0, c0, s1, c1;
        sincospif(2.0f * (scf[e0] * arg0 + scp[e0]), &s0, &c0);
        sincospif(2.0f * (scf[e1] * arg0 + scp[e1]), &s1, &c1);
        const float2 r0 = rotv[e0], r1 = rotv[e1];
        const float a0 = sca[e0], b0 = scb[e0];
        const float a1 = sca[e1], b1v = scb[e1];
        const float gr0 = sGr[e0], gi0 = sGi[e0];
        const float gr1 = sGr[e1], gi1 = sGi[e1];
        float* sprow = spart + pr * SPW;
#pragma unroll
        for (int jj = 0; jj < 17; jj++) {
            int j = j0 + jj;
            int t = ts + jj;
            if (j < SW) {
                bool ok = ((unsigned)t < (unsigned)T_LEN);
                float v0 = ok ? (a0 * s0 + b0)  : 0.f;
                float v1 = ok ? (a1 * s1 + b1v) : 0.f;
                ssig2[pr * SW + j] = make_float2(v0, v1);
                if (j >= 21 && j < 21 + TD)
                    sprow[j - 21] = gr0 * s0 + gi0 * c0 + gr1 * s1 + gi1 * c1;
            }
            float ns0 = s0 * r0.x + c0 * r0.y;
            c0 = c0 * r0.x - s0 * r0.y; s0 = ns0;
            float ns1 = s1 * r1.x + c1 * r1.y;
            c1 = c1 * r1.x - s1 * r1.y; s1 = ns1;
        }
    }
    __syncthreads();

    for (int i = tid; i < 8 * TD; i += 256) {
        int e = i >> 10, jj = i & (TD - 1);
        float2 v = ssig2[(e >> 1) * SW + 21 + jj];
        sig[((size_t)b * 8 + e) * T_LEN + t0 + jj] = (e & 1) ? v.y : v.x;
    }

    {
        const float Cv = sC;
        const bool left  = (tile == 0);
        const bool right = (tile == 7);
        float* orow = outp + (size_t)b * T_LEN + t0;
#pragma unroll
        for (int jj = tid; jj < TD; jj += 256) {
            bool skip = (left && jj < 21) || (right && jj >= TD - 21);
            if (!skip) {
                orow[jj] = spart[jj] + spart[SPW + jj] +
                           spart[2 * SPW + jj] + spart[3 * SPW + jj] + Cv;
            }
        }
    }

    {
        const bool left  = (tile == 0);
        const bool right = (tile == 7);
        const bool edge  = left || right;

        if (edge && tid < 140) {
            const int g = tid / 35, j = tid - g * 35;
            float acc = sdb0[g];
#pragma unroll
            for (int k = 0; k < KS; k++) {
                int tG = (left ? j : (T_LEN - 35 + j)) + k - 7;
                int slot = tG - t0 + 21;
                float2 w = unpk2(sdw0p[g * KS + k]);
                float2 sv = ssig2[g * SW + slot];
                acc += w.x * sv.x + w.y * sv.y;
            }
            y0e[g * 36 + j] = acc;
        }
        __syncthreads();

        if (edge && tid < 56) {
            const int g1 = tid / 28, j = tid - g1 * 28;
            float acc = sdb1[g1];
#pragma unroll
            for (int k = 0; k < KS; k++) {
                int idx; bool ok;
                if (left) { idx = j + k - 7; ok = (idx >= 0); }
                else      { idx = j + k;     ok = (idx < 35); }
                if (ok) {
                    float2 w = unpk2(sdw1p[g1 * KS + k]);
                    acc += w.x * y0e[(2 * g1) * 36 + idx]
                         + w.y * y0e[(2 * g1 + 1) * 36 + idx];
                }
            }
            y1e[g1 * 28 + j] = acc;
        }
        __syncthreads();

        if (edge && tid < 21) {
            float acc = sdb2s;
#pragma unroll
            for (int k = 0; k < KS; k++) {
                int idx; bool ok;
                if (left) { idx = tid + k - 7; ok = (idx >= 0); }
                else      { idx = tid + k;     ok = (idx < 28); }
                if (ok) {
                    float2 w = unpk2(sdw2p[k]);
                    acc += w.x * y1e[idx] + w.y * y1e[28 + idx];
                }
            }
            int tG = left ? tid : (T_LEN - 21 + tid);
            outp[(size_t)b * T_LEN + tG] = acc;
        }
    }
}

// ---------------------------------------------------------------------------
extern "C" void kernel_launch(void* const* d_in, const int* in_sizes, int n_in,
                              void* d_out, int out_size)
{
    const float* x   = (const float*)d_in[0];
    const float* W1  = (const float*)d_in[1];
    const float* b1  = (const float*)d_in[2];
    const float* W2  = (const float*)d_in[3];
    const float* b2  = (const float*)d_in[4];
    const float* fcW = (const float*)d_in[5];
    const float* fcb = (const float*)d_in[6];
    const float* dW0 = (const float*)d_in[7];
    const float* db0 = (const float*)d_in[8];
    const float* dW1 = (const float*)d_in[9];
    const float* db1 = (const float*)d_in[10];
    const float* dW2 = (const float*)d_in[11];
    const float* db2 = (const float*)d_in[12];

    float* out = (float*)d_out;
    float* outMain = out;                                        // (B, T)
    float* latent  = out + (size_t)B_SZ * T_LEN;                 // (B, E, T)
    float* sig     = latent + (size_t)B_SZ * E_CH * T_LEN;       // (B, E, T)
    float* pOut    = sig + (size_t)B_SZ * E_CH * T_LEN;          // (B, E, 1)
    float* fOut    = pOut + B_SZ * E_CH;
    float* aOut    = fOut + B_SZ * E_CH;
    float* bOut    = aOut + B_SZ * E_CH;

    const size_t smAB = (size_t)25456 * sizeof(float);           // ~99.4KB
    const size_t smD  = (size_t)(4 * (TD + 42)) * sizeof(float2)
                      + (size_t)(4 * (TD + 8) + 4 * 36 + 2 * 28) * sizeof(float);

    cudaFuncSetAttribute(latfft_kernel,   cudaFuncAttributeMaxDynamicSharedMemorySize, (int)smAB);
    cudaFuncSetAttribute(sig_tree_kernel, cudaFuncAttributeMaxDynamicSharedMemorySize, (int)smD);

    latfft_kernel<<<B_SZ * E_CH, 512, smAB>>>(x, W1, b1, W2, b2, fcW, fcb,
                                              latent, pOut, fOut, aOut, bOut);
    sig_tree_kernel<<<B_SZ * (T_LEN / TD), 256, smD>>>(pOut, fOut, aOut, bOut,
                                                       dW0, db0, dW1, db1, dW2, db2,
                                                       sig, outMain);
}

// round 15
// speedup vs baseline: 1.0300x; 1.0200x over previous
#include <cuda_runtime.h>
#include <math_constants.h>

#define T_LEN 8192
#define B_SZ  256
#define E_CH  8
#define KS    15
#define TD    1024
#define TPI_F 6.28318530717958647692f

#define PAD(i)   ((i) + ((i) >> 5))
#define F2PAD(i) ((i) + ((i) >> 4))

typedef unsigned long long ull;

// ---- packed f32x2 helpers ----
__device__ __forceinline__ ull pk2(float lo, float hi) {
    ull r;
    asm("mov.b64 %0, {%1, %2};" : "=l"(r) : "f"(lo), "f"(hi));
    return r;
}
__device__ __forceinline__ float2 unpk2(ull v) {
    float lo, hi;
    asm("mov.b64 {%0, %1}, %2;" : "=f"(lo), "=f"(hi) : "l"(v));
    return make_float2(lo, hi);
}
__device__ __forceinline__ ull fma2(ull a, ull b, ull c) {
    ull d;
    asm("fma.rn.f32x2 %0, %1, %2, %3;" : "=l"(d) : "l"(a), "l"(b), "l"(c));
    return d;
}
__device__ __forceinline__ ull add2(ull a, ull b) {
    ull d;
    asm("add.rn.f32x2 %0, %1, %2;" : "=l"(d) : "l"(a), "l"(b));
    return d;
}

__device__ __forceinline__ float2 cmulf(float2 a, float2 b) {
    return make_float2(a.x * b.x - a.y * b.y, a.x * b.y + a.y * b.x);
}
__device__ __forceinline__ float2 cadd(float2 a, float2 b) {
    return make_float2(a.x + b.x, a.y + b.y);
}
__device__ __forceinline__ float2 csub(float2 a, float2 b) {
    return make_float2(a.x - b.x, a.y - b.y);
}

// compensated float-float accumulation (TwoSum based)
__device__ __forceinline__ float2 df_add(float2 a, float2 b) {
    float s = a.x + b.x;
    float v = s - a.x;
    float e = (a.x - (s - v)) + (b.x - v);
    e = e + a.y + b.y;
    float hi = s + e;
    return make_float2(hi, e - (hi - s));
}
__device__ __forceinline__ float2 df_addf(float2 a, float b) {
    return df_add(a, make_float2(b, 0.f));
}

// ---------------------------------------------------------------------------
// Kernel A: fused per-channel dilated conv pair -> latent (B,E,T)
// Coset-blocked register streaming + packed f32x2 math. (R5 proven body.)
// ---------------------------------------------------------------------------
__global__ __launch_bounds__(256, 2) void latent_kernel(
    const float* __restrict__ x,
    const float* __restrict__ W1, const float* __restrict__ b1,
    const float* __restrict__ W2, const float* __restrict__ b2,
    float* __restrict__ latent)
{
    extern __shared__ float sm[];
    float* sx  = sm;                               // PAD(8192) -> 8448 floats
    ull*   shp = (ull*)(sm + 8448);                // F2PAD(8192) -> 8704 ull

    const int be = blockIdx.x;
    const int e  = be & 7;
    const int b  = be >> 3;
    const int d  = 1 << e;
    const int tid = threadIdx.x;

    const float* xrow = x + (size_t)b * T_LEN;
    for (int i = tid; i < T_LEN; i += 256) sx[PAD(i)] = xrow[i];

    ull w1pk[KS];
#pragma unroll
    for (int j = 0; j < KS; j++)
        w1pk[j] = pk2(W1[e * 30 + j], W1[e * 30 + 15 + j]);
    const ull bias1 = pk2(b1[2 * e], b1[2 * e + 1]);
    __syncthreads();

#pragma unroll 1
    for (int it = 0; it < 4; it++) {
        const int cc = it * 256 + tid;
        const int p  = cc & (d - 1);
        const int qc = cc >> e;
        const int tb = p + (qc << (e + 3));
        ull xd[22];
#pragma unroll
        for (int m = 0; m < 22; m++) {
            int idx = tb + (m - 7) * d;
            float v = ((unsigned)idx < (unsigned)T_LEN) ? sx[PAD(idx)] : 0.f;
            xd[m] = pk2(v, v);
        }
#pragma unroll
        for (int rr = 0; rr < 8; rr++) {
            ull a0 = bias1, a1 = 0ULL;
#pragma unroll
            for (int j = 0; j < KS; j += 2) a0 = fma2(w1pk[j], xd[rr + j], a0);
#pragma unroll
            for (int j = 1; j < KS; j += 2) a1 = fma2(w1pk[j], xd[rr + j], a1);
            shp[F2PAD(tb + rr * d)] = add2(a0, a1);
        }
    }

    ull w2pk[KS];
#pragma unroll
    for (int k = 0; k < KS; k++)
        w2pk[k] = pk2(W2[e * 30 + k], W2[e * 30 + 15 + k]);
    const ull bias2 = pk2(b2[e], 0.f);
    __syncthreads();

#pragma unroll 1
    for (int it = 0; it < 4; it++) {
        const int cc = it * 256 + tid;
        const int p  = cc & (d - 1);
        const int qc = cc >> e;
        const int tb = p + (qc << (e + 3));
        ull gp[22];
#pragma unroll
        for (int m = 0; m < 22; m++) {
            int idx = tb + (m - 7) * d;
            gp[m] = ((unsigned)idx < (unsigned)T_LEN) ? shp[F2PAD(idx)] : 0ULL;
        }
#pragma unroll
        for (int rr = 0; rr < 8; rr++) {
            ull a0 = bias2, a1 = 0ULL;
#pragma unroll
            for (int k = 0; k < KS; k += 2) a0 = fma2(w2pk[k], gp[rr + k], a0);
#pragma unroll
            for (int k = 1; k < KS; k += 2) a1 = fma2(w2pk[k], gp[rr + k], a1);
            float2 r = unpk2(add2(a0, a1));
            sx[PAD(tb + rr * d)] = r.x + r.y;
        }
    }
    __syncthreads();

    float* lrow = latent + (size_t)be * T_LEN;
    for (int i = tid; i < T_LEN; i += 256) lrow[i] = sx[PAD(i)];
}

// ---------------------------------------------------------------------------
// Kernel B: per-(b,e) row — fc dots, real FFT (8192 real via complex 4096),
// radix-8 Stockham, stage-0 fused with load, stage-3 outputs in registers,
// slim fp32 reductions. Reduction twiddles W_k = tw2[tid] * e^{-i pi q/8}
// (constant rotation) — eliminates 8 __sincosf/thread of MUFU pressure.
// ---------------------------------------------------------------------------
__global__ __launch_bounds__(512, 2) void fft_kernel(
    const float* __restrict__ latent,
    const float* __restrict__ fcW, const float* __restrict__ fcb,
    float* __restrict__ pOut, float* __restrict__ fOut,
    float* __restrict__ aOut, float* __restrict__ bOut)
{
    const int M = 4096;
    extern __shared__ float smf[];
    float2* bufA = (float2*)smf;
    float2* bufB = bufA + 4352;
    float2* tw   = bufB + 4352;          // 512: e^{-2pi i j/4096}
    float2* tw2  = tw + 512;             // 512: e^{-pi i j/4096}
    __shared__ float red[64];

    const int be = blockIdx.x;
    const int e  = be & 7;
    const int tid = threadIdx.x;
    const float RS = 0.70710678118654752440f;

    const float2* rowc = (const float2*)(latent + (size_t)be * T_LEN);
    const float2* fw0  = (const float2*)(fcW + (size_t)(e * 2 + 0) * T_LEN);
    const float2* fw1  = (const float2*)(fcW + (size_t)(e * 2 + 1) * T_LEN);

    float2 v0 = make_float2(0.f, 0.f), v1 = make_float2(0.f, 0.f);
    float2 z[8];
#pragma unroll
    for (int q = 0; q < 8; q++) {
        const int i = tid + 512 * q;
        float2 zz = rowc[i];
        z[q] = zz;
        float2 a0 = fw0[i], a1 = fw1[i];
        v0 = df_addf(v0, zz.x * a0.x + zz.y * a0.y);
        v1 = df_addf(v1, zz.x * a1.x + zz.y * a1.y);
    }
    {
        float s, c;
        sincosf(-(float)CUDART_PI * (float)tid / 2048.0f, &s, &c);
        tw[tid] = make_float2(c, s);
        sincosf(-(float)CUDART_PI * (float)tid / 4096.0f, &s, &c);
        tw2[tid] = make_float2(c, s);
    }
    {
        float2 t0 = cadd(z[0], z[4]), t1 = csub(z[0], z[4]);
        float2 t2 = cadd(z[2], z[6]), t3 = csub(z[2], z[6]);
        float2 E0 = cadd(t0, t2);
        float2 E1 = make_float2(t1.x + t3.y, t1.y - t3.x);
        float2 E2 = csub(t0, t2);
        float2 E3 = make_float2(t1.x - t3.y, t1.y + t3.x);
        float2 s0 = cadd(z[1], z[5]), s1 = csub(z[1], z[5]);
        float2 s2 = cadd(z[3], z[7]), s3 = csub(z[3], z[7]);
        float2 O0 = cadd(s0, s2);
        float2 O1 = make_float2(s1.x + s3.y, s1.y - s3.x);
        float2 O2 = csub(s0, s2);
        float2 O3 = make_float2(s1.x - s3.y, s1.y + s3.x);
        float2 Q1 = make_float2(RS * (O1.x + O1.y), RS * (O1.y - O1.x));
        float2 Q2 = make_float2(O2.y, -O2.x);
        float2 Q3 = make_float2(RS * (O3.y - O3.x), -RS * (O3.x + O3.y));
        const int ob = tid << 3;
        bufA[F2PAD(ob)]     = cadd(E0, O0);
        bufA[F2PAD(ob + 1)] = cadd(E1, Q1);
        bufA[F2PAD(ob + 2)] = cadd(E2, Q2);
        bufA[F2PAD(ob + 3)] = cadd(E3, Q3);
        bufA[F2PAD(ob + 4)] = csub(E0, O0);
        bufA[F2PAD(ob + 5)] = csub(E1, Q1);
        bufA[F2PAD(ob + 6)] = csub(E2, Q2);
        bufA[F2PAD(ob + 7)] = csub(E3, Q3);
    }
    __syncthreads();

    float2* bin  = bufA;
    float2* bout = bufB;
#pragma unroll
    for (int sg = 1; sg <= 2; sg++) {
        const int m = 1 << (3 * sg);
        const int idx = tid;
        const int r = idx & (m - 1);
        float2 W = tw[r << (9 - 3 * sg)];

        float2 u0 = bin[F2PAD(idx)];
        float2 z1 = bin[F2PAD(idx + 512)];
        float2 z2 = bin[F2PAD(idx + 1024)];
        float2 z3 = bin[F2PAD(idx + 1536)];
        float2 z4 = bin[F2PAD(idx + 2048)];
        float2 z5 = bin[F2PAD(idx + 2560)];
        float2 z6 = bin[F2PAD(idx + 3072)];
        float2 z7 = bin[F2PAD(idx + 3584)];

        float2 W2 = cmulf(W, W);
        float2 W3 = cmulf(W2, W);
        float2 W4 = cmulf(W2, W2);
        float2 W5 = cmulf(W4, W);
        float2 W6 = cmulf(W4, W2);
        float2 W7 = cmulf(W4, W3);

        float2 u1 = cmulf(z1, W);
        float2 u2 = cmulf(z2, W2);
        float2 u3 = cmulf(z3, W3);
        float2 u4 = cmulf(z4, W4);
        float2 u5 = cmulf(z5, W5);
        float2 u6 = cmulf(z6, W6);
        float2 u7 = cmulf(z7, W7);

        float2 t0 = cadd(u0, u4), t1 = csub(u0, u4);
        float2 t2 = cadd(u2, u6), t3 = csub(u2, u6);
        float2 E0 = cadd(t0, t2);
        float2 E1 = make_float2(t1.x + t3.y, t1.y - t3.x);
        float2 E2 = csub(t0, t2);
        float2 E3 = make_float2(t1.x - t3.y, t1.y + t3.x);
        float2 s0 = cadd(u1, u5), s1 = csub(u1, u5);
        float2 s2 = cadd(u3, u7), s3 = csub(u3, u7);
        float2 O0 = cadd(s0, s2);
        float2 O1 = make_float2(s1.x + s3.y, s1.y - s3.x);
        float2 O2 = csub(s0, s2);
        float2 O3 = make_float2(s1.x - s3.y, s1.y + s3.x);
        float2 Q1 = make_float2(RS * (O1.x + O1.y), RS * (O1.y - O1.x));
        float2 Q2 = make_float2(O2.y, -O2.x);
        float2 Q3 = make_float2(RS * (O3.y - O3.x), -RS * (O3.x + O3.y));

        const int ob = ((idx - r) << 3) + r;
        bout[F2PAD(ob)]         = cadd(E0, O0);
        bout[F2PAD(ob + m)]     = cadd(E1, Q1);
        bout[F2PAD(ob + 2 * m)] = cadd(E2, Q2);
        bout[F2PAD(ob + 3 * m)] = cadd(E3, Q3);
        bout[F2PAD(ob + 4 * m)] = csub(E0, O0);
        bout[F2PAD(ob + 5 * m)] = csub(E1, Q1);
        bout[F2PAD(ob + 6 * m)] = csub(E2, Q2);
        bout[F2PAD(ob + 7 * m)] = csub(E3, Q3);
        __syncthreads();
        float2* tmp = bin; bin = bout; bout = tmp;
    }

    {
        const int idx = tid;
        float2 W = tw[idx];

        float2 u0 = bin[F2PAD(idx)];
        float2 z1 = bin[F2PAD(idx + 512)];
        float2 z2 = bin[F2PAD(idx + 1024)];
        float2 z3 = bin[F2PAD(idx + 1536)];
        float2 z4 = bin[F2PAD(idx + 2048)];
        float2 z5 = bin[F2PAD(idx + 2560)];
        float2 z6 = bin[F2PAD(idx + 3072)];
        float2 z7 = bin[F2PAD(idx + 3584)];

        float2 W2 = cmulf(W, W);
        float2 W3 = cmulf(W2, W);
        float2 W4 = cmulf(W2, W2);
        float2 W5 = cmulf(W4, W);
        float2 W6 = cmulf(W4, W2);
        float2 W7 = cmulf(W4, W3);

        float2 u1 = cmulf(z1, W);
        float2 u2 = cmulf(z2, W2);
        float2 u3 = cmulf(z3, W3);
        float2 u4 = cmulf(z4, W4);
        float2 u5 = cmulf(z5, W5);
        float2 u6 = cmulf(z6, W6);
        float2 u7 = cmulf(z7, W7);

        float2 t0 = cadd(u0, u4), t1 = csub(u0, u4);
        float2 t2 = cadd(u2, u6), t3 = csub(u2, u6);
        float2 E0 = cadd(t0, t2);
        float2 E1 = make_float2(t1.x + t3.y, t1.y - t3.x);
        float2 E2 = csub(t0, t2);
        float2 E3 = make_float2(t1.x - t3.y, t1.y + t3.x);
        float2 s0 = cadd(u1, u5), s1 = csub(u1, u5);
        float2 s2 = cadd(u3, u7), s3 = csub(u3, u7);
        float2 O0 = cadd(s0, s2);
        float2 O1 = make_float2(s1.x + s3.y, s1.y - s3.x);
        float2 O2 = csub(s0, s2);
        float2 O3 = make_float2(s1.x - s3.y, s1.y + s3.x);
        float2 Q1 = make_float2(RS * (O1.x + O1.y), RS * (O1.y - O1.x));
        float2 Q2 = make_float2(O2.y, -O2.x);
        float2 Q3 = make_float2(RS * (O3.y - O3.x), -RS * (O3.x + O3.y));

        z[0] = cadd(E0, O0); z[1] = cadd(E1, Q1);
        z[2] = cadd(E2, Q2); z[3] = cadd(E3, Q3);
        z[4] = csub(E0, O0); z[5] = csub(E1, Q1);
        z[6] = csub(E2, Q2); z[7] = csub(E3, Q3);
#pragma unroll
        for (int q = 0; q < 8; q++)
            bout[F2PAD(idx + 512 * q)] = z[q];
    }
    __syncthreads();
    // bout holds Z_k natural order; thread tid holds z[q] = Z_{tid+512q}

    // ---- reduction: twiddle fix W_k = tw2[tid] * e^{-i pi q / 8} ----
    const float CQ[8] = { 1.0f, 0.92387953251f, 0.70710678119f, 0.38268343236f,
                          0.0f, -0.38268343236f, -0.70710678119f, -0.92387953251f };
    const float SQ[8] = { 0.0f, -0.38268343236f, -0.70710678119f, -0.92387953251f,
                          -1.0f, -0.92387953251f, -0.70710678119f, -0.38268343236f };
    const float2 Wb = tw2[tid];

    float psum = 0.f, wsum = 0.f;
#pragma unroll
    for (int q = 0; q < 8; q++) {
        const int k = tid + 512 * q;
        if (k > 0) {
            float2 zk = z[q];
            float2 zm = bout[F2PAD(M - k)];
            float Ax = 0.5f * (zk.x + zm.x), Ay = 0.5f * (zk.y - zm.y);
            float Bx = 0.5f * (zk.x - zm.x), By = 0.5f * (zk.y + zm.y);
            float c = Wb.x * CQ[q] - Wb.y * SQ[q];
            float s = Wb.x * SQ[q] + Wb.y * CQ[q];
            float Xr = Ax + c * By + s * Bx;
            float Xi = Ay - c * Bx + s * By;
            float pw = Xr * Xr + Xi * Xi;
            psum += pw;
            wsum = fmaf((float)k, pw, wsum);
        }
    }
    if (tid == 0) {
        float xm = z[0].x - z[0].y;
        psum += xm * xm;
        wsum = fmaf((float)M, xm * xm, wsum);
    }

    float v0s = v0.x + v0.y;
    float v1s = v1.x + v1.y;

    const unsigned mask = 0xffffffffu;
#pragma unroll
    for (int o = 16; o > 0; o >>= 1) {
        psum += __shfl_down_sync(mask, psum, o);
        wsum += __shfl_down_sync(mask, wsum, o);
        v0s  += __shfl_down_sync(mask, v0s, o);
        v1s  += __shfl_down_sync(mask, v1s, o);
    }
    const int warp = tid >> 5, lane = tid & 31;
    if (lane == 0) {
        red[warp] = psum; red[16 + warp] = wsum;
        red[32 + warp] = v0s; red[48 + warp] = v1s;
    }
    __syncthreads();
    if (tid == 0) {
        double P = 0, Wm = 0, V0 = 0, V1 = 0;
        for (int i = 0; i < 16; i++) {
            P  += (double)red[i];
            Wm += (double)red[16 + i];
            V0 += (double)red[32 + i];
            V1 += (double)red[48 + i];
        }
        V0 += (double)fcb[e * 2];
        V1 += (double)fcb[e * 2 + 1];
        float f    = (float)(0.5 * Wm / P);
        float a    = 2.0f * sqrtf((float)P) / (float)T_LEN;
        float boff = (z[0].x + z[0].y) / (float)T_LEN;
        float p    = atan2f((float)V1, (float)V0) / TPI_F;
        pOut[be] = p; fOut[be] = f; aOut[be] = a; bOut[be] = boff;
    }
}

// ---------------------------------------------------------------------------
// Kernel D: sinusoid resynthesis + ANALYTIC deconv tree. (R9/R11 proven.)
// ---------------------------------------------------------------------------
__global__ __launch_bounds__(256) void sig_tree_kernel(
    const float* __restrict__ pArr, const float* __restrict__ fArr,
    const float* __restrict__ aArr, const float* __restrict__ bArr,
    const float* __restrict__ dW0, const float* __restrict__ db0,
    const float* __restrict__ dW1, const float* __restrict__ db1,
    const float* __restrict__ dW2, const float* __restrict__ db2,
    float* __restrict__ sig, float* __restrict__ outp)
{
    extern __shared__ float smd[];
    const int SW  = TD + 42;
    const int SPW = TD + 8;
    float2* ssig2 = (float2*)smd;
    float*  spart = (float*)(ssig2 + 4 * SW);
    float*  y0e   = spart + 4 * SPW;
    float*  y1e   = y0e + 4 * 36;

    __shared__ float sca[8], scf[8], scp[8], scb[8];
    __shared__ float2 rotv[8];
    __shared__ float sGr[8], sGi[8];
    __shared__ float sC;
    __shared__ ull sdw0p[4 * KS], sdw1p[2 * KS], sdw2p[KS];
    __shared__ float sdb0[4], sdb1[2], sdb2s;

    const int blk  = blockIdx.x;
    const int tile = blk & 7;
    const int b    = blk >> 3;
    const int t0   = tile * TD;
    const int tid  = threadIdx.x;
    const float inv = 2.0f / (float)(T_LEN - 1);

    if (tid < 8) {
        const int e = tid;
        float fv = fArr[b * 8 + e];
        float av = aArr[b * 8 + e];
        sca[e] = av; scf[e] = fv;
        scp[e] = pArr[b * 8 + e]; scb[e] = bArr[b * 8 + e];
        float S, C;
        sincospif(2.0f * fv * inv, &S, &C);
        rotv[e] = make_float2(C, S);

        float h0r = 0.f, h0i = 0.f, h1r = 0.f, h1i = 0.f, h2r = 0.f, h2i = 0.f;
        const int row1 = ((e >> 2) << 1) | ((e >> 1) & 1);
        const int row2 = e >> 2;
#pragma unroll
        for (int k = 0; k < KS; k++) {
            float ph = 2.0f * fv * (float)(k - 7) * inv;
            float ss, cc;
            sincospif(ph, &ss, &cc);
            float w0 = dW0[e * KS + k];
            float w1 = dW1[row1 * KS + k];
            float w2 = dW2[row2 * KS + k];
            h0r += w0 * cc; h0i += w0 * ss;
            h1r += w1 * cc; h1i += w1 * ss;
            h2r += w2 * cc; h2i += w2 * ss;
        }
        float g1r = h0r * h1r - h0i * h1i;
        float g1i = h0r * h1i + h0i * h1r;
        sGr[e] = av * (g1r * h2r - g1i * h2i);
        sGi[e] = av * (g1r * h2i + g1i * h2r);
    }
    if (tid == 8) {
        float S0[8], S1[4], S2[2];
        for (int e2 = 0; e2 < 8; e2++) {
            float s = 0.f;
            for (int k = 0; k < KS; k++) s += dW0[e2 * KS + k];
            S0[e2] = s;
        }
        for (int g = 0; g < 4; g++) {
            float s = 0.f;
            for (int k = 0; k < KS; k++) s += dW1[g * KS + k];
            S1[g] = s;
        }
        for (int q = 0; q < 2; q++) {
            float s = 0.f;
            for (int k = 0; k < KS; k++) s += dW2[q * KS + k];
            S2[q] = s;
        }
        float Cv = db2[0];
        for (int q = 0; q < 2; q++) Cv += S2[q] * db1[q];
        for (int g = 0; g < 4; g++) Cv += S2[g >> 1] * S1[g] * db0[g];
        for (int e2 = 0; e2 < 8; e2++)
            Cv += S2[e2 >> 2] * S1[e2 >> 1] * S0[e2] * bArr[b * 8 + e2];
        sC = Cv;
    }
    if (tid < 4 * KS) {
        int g = tid / KS, k = tid - g * KS;
        sdw0p[tid] = pk2(dW0[(2 * g) * KS + k], dW0[(2 * g + 1) * KS + k]);
    }
    if (tid < 2 * KS) {
        int g = tid / KS, k = tid - g * KS;
        sdw1p[tid] = pk2(dW1[(2 * g) * KS + k], dW1[(2 * g + 1) * KS + k]);
    }
    if (tid < KS) sdw2p[tid] = pk2(dW2[tid], dW2[KS + tid]);
    if (tid < 4) sdb0[tid] = db0[tid];
    if (tid < 2) sdb1[tid] = db1[tid];
    if (tid == 0) sdb2s = db2[0];
    __syncthreads();

    {
        const int pr  = tid >> 6;
        const int sub = tid & 63;
        const int j0  = sub * 17;
        const int ts  = t0 - 21 + j0;
        const int e0 = 2 * pr, e1 = 2 * pr + 1;
        const float arg0 = -1.0f + (float)ts * inv;
        float s0, c0, s1, c1;
        sincospif(2.0f * (scf[e0] * arg0 + scp[e0]), &s0, &c0);
        sincospif(2.0f * (scf[e1] * arg0 + scp[e1]), &s1, &c1);
        const float2 r0 = rotv[e0], r1 = rotv[e1];
        const float a0 = sca[e0], b0 = scb[e0];
        const float a1 = sca[e1], b1v = scb[e1];
        const float gr0 = sGr[e0], gi0 = sGi[e0];
        const float gr1 = sGr[e1], gi1 = sGi[e1];
        float* sprow = spart + pr * SPW;
#pragma unroll
        for (int jj = 0; jj < 17; jj++) {
            int j = j0 + jj;
            int t = ts + jj;
            if (j < SW) {
                bool ok = ((unsigned)t < (unsigned)T_LEN);
                float v0 = ok ? (a0 * s0 + b0)  : 0.f;
                float v1 = ok ? (a1 * s1 + b1v) : 0.f;
                ssig2[pr * SW + j] = make_float2(v0, v1);
                if (j >= 21 && j < 21 + TD)
                    sprow[j - 21] = gr0 * s0 + gi0 * c0 + gr1 * s1 + gi1 * c1;
            }
            float ns0 = s0 * r0.x + c0 * r0.y;
            c0 = c0 * r0.x - s0 * r0.y; s0 = ns0;
            float ns1 = s1 * r1.x + c1 * r1.y;
            c1 = c1 * r1.x - s1 * r1.y; s1 = ns1;
        }
    }
    __syncthreads();

    for (int i = tid; i < 8 * TD; i += 256) {
        int e = i >> 10, jj = i & (TD - 1);
        float2 v = ssig2[(e >> 1) * SW + 21 + jj];
        sig[((size_t)b * 8 + e) * T_LEN + t0 + jj] = (e & 1) ? v.y : v.x;
    }

    {
        const float Cv = sC;
        const bool left  = (tile == 0);
        const bool right = (tile == 7);
        float* orow = outp + (size_t)b * T_LEN + t0;
#pragma unroll
        for (int jj = tid; jj < TD; jj += 256) {
            bool skip = (left && jj < 21) || (right && jj >= TD - 21);
            if (!skip) {
                orow[jj] = spart[jj] + spart[SPW + jj] +
                           spart[2 * SPW + jj] + spart[3 * SPW + jj] + Cv;
            }
        }
    }

    {
        const bool left  = (tile == 0);
        const bool right = (tile == 7);
        const bool edge  = left || right;

        if (edge && tid < 140) {
            const int g = tid / 35, j = tid - g * 35;
            float acc = sdb0[g];
#pragma unroll
            for (int k = 0; k < KS; k++) {
                int tG = (left ? j : (T_LEN - 35 + j)) + k - 7;
                int slot = tG - t0 + 21;
                float2 w = unpk2(sdw0p[g * KS + k]);
                float2 sv = ssig2[g * SW + slot];
                acc += w.x * sv.x + w.y * sv.y;
            }
            y0e[g * 36 + j] = acc;
        }
        __syncthreads();

        if (edge && tid < 56) {
            const int g1 = tid / 28, j = tid - g1 * 28;
            float acc = sdb1[g1];
#pragma unroll
            for (int k = 0; k < KS; k++) {
                int idx; bool ok;
                if (left) { idx = j + k - 7; ok = (idx >= 0); }
                else      { idx = j + k;     ok = (idx < 35); }
                if (ok) {
                    float2 w = unpk2(sdw1p[g1 * KS + k]);
                    acc += w.x * y0e[(2 * g1) * 36 + idx]
                         + w.y * y0e[(2 * g1 + 1) * 36 + idx];
                }
            }
            y1e[g1 * 28 + j] = acc;
        }
        __syncthreads();

        if (edge && tid < 21) {
            float acc = sdb2s;
#pragma unroll
            for (int k = 0; k < KS; k++) {
                int idx; bool ok;
                if (left) { idx = tid + k - 7; ok = (idx >= 0); }
                else      { idx = tid + k;     ok = (idx < 28); }
                if (ok) {
                    float2 w = unpk2(sdw2p[k]);
                    acc += w.x * y1e[idx] + w.y * y1e[28 + idx];
                }
            }
            int tG = left ? tid : (T_LEN - 21 + tid);
            outp[(size_t)b * T_LEN + tG] = acc;
        }
    }
}

// ---------------------------------------------------------------------------
extern "C" void kernel_launch(void* const* d_in, const int* in_sizes, int n_in,
                              void* d_out, int out_size)
{
    const float* x   = (const float*)d_in[0];
    const float* W1  = (const float*)d_in[1];
    const float* b1  = (const float*)d_in[2];
    const float* W2  = (const float*)d_in[3];
    const float* b2  = (const float*)d_in[4];
    const float* fcW = (const float*)d_in[5];
    const float* fcb = (const float*)d_in[6];
    const float* dW0 = (const float*)d_in[7];
    const float* db0 = (const float*)d_in[8];
    const float* dW1 = (const float*)d_in[9];
    const float* db1 = (const float*)d_in[10];
    const float* dW2 = (const float*)d_in[11];
    const float* db2 = (const float*)d_in[12];

    float* out = (float*)d_out;
    float* outMain = out;                                        // (B, T)
    float* latent  = out + (size_t)B_SZ * T_LEN;                 // (B, E, T)
    float* sig     = latent + (size_t)B_SZ * E_CH * T_LEN;       // (B, E, T)
    float* pOut    = sig + (size_t)B_SZ * E_CH * T_LEN;          // (B, E, 1)
    float* fOut    = pOut + B_SZ * E_CH;
    float* aOut    = fOut + B_SZ * E_CH;
    float* bOut    = aOut + B_SZ * E_CH;

    const size_t smA = (size_t)8448 * sizeof(float) + (size_t)8704 * sizeof(ull);
    const size_t smB = (size_t)(4352 * 2 + 512 + 512) * sizeof(float2);
    const size_t smD = (size_t)(4 * (TD + 42)) * sizeof(float2)
                     + (size_t)(4 * (TD + 8) + 4 * 36 + 2 * 28) * sizeof(float);

    cudaFuncSetAttribute(latent_kernel,   cudaFuncAttributeMaxDynamicSharedMemorySize, (int)smA);
    cudaFuncSetAttribute(fft_kernel,      cudaFuncAttributeMaxDynamicSharedMemorySize, (int)smB);
    cudaFuncSetAttribute(sig_tree_kernel, cudaFuncAttributeMaxDynamicSharedMemorySize, (int)smD);

    latent_kernel<<<B_SZ * E_CH, 256, smA>>>(x, W1, b1, W2, b2, latent);
    fft_kernel<<<B_SZ * E_CH, 512, smB>>>(latent, fcW, fcb, pOut, fOut, aOut, bOut);
    sig_tree_kernel<<<B_SZ * (T_LEN / TD), 256, smD>>>(pOut, fOut, aOut, bOut,
                                                       dW0, db0, dW1, db1, dW2, db2,
                                                       sig, outMain);
}

// round 16
// speedup vs baseline: 1.1254x; 1.0926x over previous
#include <cuda_runtime.h>
#include <math_constants.h>

#define T_LEN 8192
#define B_SZ  256
#define E_CH  8
#define KS    15
#define TD    1024
#define TPI_F 6.28318530717958647692f

#define PAD(i)   ((i) + ((i) >> 5))
#define F2PAD(i) ((i) + ((i) >> 4))

typedef unsigned long long ull;

// ---- packed f32x2 helpers ----
__device__ __forceinline__ ull pk2(float lo, float hi) {
    ull r;
    asm("mov.b64 %0, {%1, %2};" : "=l"(r) : "f"(lo), "f"(hi));
    return r;
}
__device__ __forceinline__ float2 unpk2(ull v) {
    float lo, hi;
    asm("mov.b64 {%0, %1}, %2;" : "=f"(lo), "=f"(hi) : "l"(v));
    return make_float2(lo, hi);
}
__device__ __forceinline__ ull fma2(ull a, ull b, ull c) {
    ull d;
    asm("fma.rn.f32x2 %0, %1, %2, %3;" : "=l"(d) : "l"(a), "l"(b), "l"(c));
    return d;
}
__device__ __forceinline__ ull add2(ull a, ull b) {
    ull d;
    asm("add.rn.f32x2 %0, %1, %2;" : "=l"(d) : "l"(a), "l"(b));
    return d;
}

__device__ __forceinline__ float2 cmulf(float2 a, float2 b) {
    return make_float2(a.x * b.x - a.y * b.y, a.x * b.y + a.y * b.x);
}
__device__ __forceinline__ float2 cadd(float2 a, float2 b) {
    return make_float2(a.x + b.x, a.y + b.y);
}
__device__ __forceinline__ float2 csub(float2 a, float2 b) {
    return make_float2(a.x - b.x, a.y - b.y);
}

// compensated float-float accumulation (TwoSum based)
__device__ __forceinline__ float2 df_add(float2 a, float2 b) {
    float s = a.x + b.x;
    float v = s - a.x;
    float e = (a.x - (s - v)) + (b.x - v);
    e = e + a.y + b.y;
    float hi = s + e;
    return make_float2(hi, e - (hi - s));
}
__device__ __forceinline__ float2 df_addf(float2 a, float b) {
    return df_add(a, make_float2(b, 0.f));
}

// ---------------------------------------------------------------------------
// Kernel A: fused per-channel dilated conv pair -> latent (B,E,T)
// Coset-blocked register streaming + packed f32x2 math. (R5 proven body.)
// ---------------------------------------------------------------------------
__global__ __launch_bounds__(256, 2) void latent_kernel(
    const float* __restrict__ x,
    const float* __restrict__ W1, const float* __restrict__ b1,
    const float* __restrict__ W2, const float* __restrict__ b2,
    float* __restrict__ latent)
{
    extern __shared__ float sm[];
    float* sx  = sm;                               // PAD(8192) -> 8448 floats
    ull*   shp = (ull*)(sm + 8448);                // F2PAD(8192) -> 8704 ull

    const int be = blockIdx.x;
    const int e  = be & 7;
    const int b  = be >> 3;
    const int d  = 1 << e;
    const int tid = threadIdx.x;

    const float* xrow = x + (size_t)b * T_LEN;
    for (int i = tid; i < T_LEN; i += 256) sx[PAD(i)] = xrow[i];

    ull w1pk[KS];
#pragma unroll
    for (int j = 0; j < KS; j++)
        w1pk[j] = pk2(W1[e * 30 + j], W1[e * 30 + 15 + j]);
    const ull bias1 = pk2(b1[2 * e], b1[2 * e + 1]);
    __syncthreads();

#pragma unroll 1
    for (int it = 0; it < 4; it++) {
        const int cc = it * 256 + tid;
        const int p  = cc & (d - 1);
        const int qc = cc >> e;
        const int tb = p + (qc << (e + 3));
        ull xd[22];
#pragma unroll
        for (int m = 0; m < 22; m++) {
            int idx = tb + (m - 7) * d;
            float v = ((unsigned)idx < (unsigned)T_LEN) ? sx[PAD(idx)] : 0.f;
            xd[m] = pk2(v, v);
        }
#pragma unroll
        for (int rr = 0; rr < 8; rr++) {
            ull a0 = bias1, a1 = 0ULL;
#pragma unroll
            for (int j = 0; j < KS; j += 2) a0 = fma2(w1pk[j], xd[rr + j], a0);
#pragma unroll
            for (int j = 1; j < KS; j += 2) a1 = fma2(w1pk[j], xd[rr + j], a1);
            shp[F2PAD(tb + rr * d)] = add2(a0, a1);
        }
    }

    ull w2pk[KS];
#pragma unroll
    for (int k = 0; k < KS; k++)
        w2pk[k] = pk2(W2[e * 30 + k], W2[e * 30 + 15 + k]);
    const ull bias2 = pk2(b2[e], 0.f);
    __syncthreads();

#pragma unroll 1
    for (int it = 0; it < 4; it++) {
        const int cc = it * 256 + tid;
        const int p  = cc & (d - 1);
        const int qc = cc >> e;
        const int tb = p + (qc << (e + 3));
        ull gp[22];
#pragma unroll
        for (int m = 0; m < 22; m++) {
            int idx = tb + (m - 7) * d;
            gp[m] = ((unsigned)idx < (unsigned)T_LEN) ? shp[F2PAD(idx)] : 0ULL;
        }
#pragma unroll
        for (int rr = 0; rr < 8; rr++) {
            ull a0 = bias2, a1 = 0ULL;
#pragma unroll
            for (int k = 0; k < KS; k += 2) a0 = fma2(w2pk[k], gp[rr + k], a0);
#pragma unroll
            for (int k = 1; k < KS; k += 2) a1 = fma2(w2pk[k], gp[rr + k], a1);
            float2 r = unpk2(add2(a0, a1));
            sx[PAD(tb + rr * d)] = r.x + r.y;
        }
    }
    __syncthreads();

    float* lrow = latent + (size_t)be * T_LEN;
    for (int i = tid; i < T_LEN; i += 256) lrow[i] = sx[PAD(i)];
}

// ---------------------------------------------------------------------------
// Kernel B: per-(b,e) row — fc dots, real FFT (8192 real via complex 4096),
// radix-8 Stockham, stage-0 fused with load, stage-3 outputs in registers,
// slim fp32 reductions. 3 blocks/SM (48 warps) — smem 73.7KB fits 3x.
// ---------------------------------------------------------------------------
__global__ __launch_bounds__(512, 3) void fft_kernel(
    const float* __restrict__ latent,
    const float* __restrict__ fcW, const float* __restrict__ fcb,
    float* __restrict__ pOut, float* __restrict__ fOut,
    float* __restrict__ aOut, float* __restrict__ bOut)
{
    const int M = 4096;
    extern __shared__ float smf[];
    float2* bufA = (float2*)smf;
    float2* bufB = bufA + 4352;
    float2* tw   = bufB + 4352;
    __shared__ float red[64];

    const int be = blockIdx.x;
    const int e  = be & 7;
    const int tid = threadIdx.x;
    const float RS = 0.70710678118654752440f;

    const float2* rowc = (const float2*)(latent + (size_t)be * T_LEN);
    const float2* fw0  = (const float2*)(fcW + (size_t)(e * 2 + 0) * T_LEN);
    const float2* fw1  = (const float2*)(fcW + (size_t)(e * 2 + 1) * T_LEN);

    float2 v0 = make_float2(0.f, 0.f), v1 = make_float2(0.f, 0.f);
    float2 z[8];
#pragma unroll
    for (int q = 0; q < 8; q++) {
        const int i = tid + 512 * q;
        float2 zz = rowc[i];
        z[q] = zz;
        float2 a0 = fw0[i], a1 = fw1[i];
        v0 = df_addf(v0, zz.x * a0.x + zz.y * a0.y);
        v1 = df_addf(v1, zz.x * a1.x + zz.y * a1.y);
    }
    {
        float s, c;
        sincosf(-(float)CUDART_PI * (float)tid / 2048.0f, &s, &c);
        tw[tid] = make_float2(c, s);
    }
    {
        float2 t0 = cadd(z[0], z[4]), t1 = csub(z[0], z[4]);
        float2 t2 = cadd(z[2], z[6]), t3 = csub(z[2], z[6]);
        float2 E0 = cadd(t0, t2);
        float2 E1 = make_float2(t1.x + t3.y, t1.y - t3.x);
        float2 E2 = csub(t0, t2);
        float2 E3 = make_float2(t1.x - t3.y, t1.y + t3.x);
        float2 s0 = cadd(z[1], z[5]), s1 = csub(z[1], z[5]);
        float2 s2 = cadd(z[3], z[7]), s3 = csub(z[3], z[7]);
        float2 O0 = cadd(s0, s2);
        float2 O1 = make_float2(s1.x + s3.y, s1.y - s3.x);
        float2 O2 = csub(s0, s2);
        float2 O3 = make_float2(s1.x - s3.y, s1.y + s3.x);
        float2 Q1 = make_float2(RS * (O1.x + O1.y), RS * (O1.y - O1.x));
        float2 Q2 = make_float2(O2.y, -O2.x);
        float2 Q3 = make_float2(RS * (O3.y - O3.x), -RS * (O3.x + O3.y));
        const int ob = tid << 3;
        bufA[F2PAD(ob)]     = cadd(E0, O0);
        bufA[F2PAD(ob + 1)] = cadd(E1, Q1);
        bufA[F2PAD(ob + 2)] = cadd(E2, Q2);
        bufA[F2PAD(ob + 3)] = cadd(E3, Q3);
        bufA[F2PAD(ob + 4)] = csub(E0, O0);
        bufA[F2PAD(ob + 5)] = csub(E1, Q1);
        bufA[F2PAD(ob + 6)] = csub(E2, Q2);
        bufA[F2PAD(ob + 7)] = csub(E3, Q3);
    }
    __syncthreads();

    float2* bin  = bufA;
    float2* bout = bufB;
#pragma unroll
    for (int sg = 1; sg <= 2; sg++) {
        const int m = 1 << (3 * sg);
        const int idx = tid;
        const int r = idx & (m - 1);
        float2 W = tw[r << (9 - 3 * sg)];

        float2 u0 = bin[F2PAD(idx)];
        float2 z1 = bin[F2PAD(idx + 512)];
        float2 z2 = bin[F2PAD(idx + 1024)];
        float2 z3 = bin[F2PAD(idx + 1536)];
        float2 z4 = bin[F2PAD(idx + 2048)];
        float2 z5 = bin[F2PAD(idx + 2560)];
        float2 z6 = bin[F2PAD(idx + 3072)];
        float2 z7 = bin[F2PAD(idx + 3584)];

        float2 W2 = cmulf(W, W);
        float2 W3 = cmulf(W2, W);
        float2 W4 = cmulf(W2, W2);
        float2 W5 = cmulf(W4, W);
        float2 W6 = cmulf(W4, W2);
        float2 W7 = cmulf(W4, W3);

        float2 u1 = cmulf(z1, W);
        float2 u2 = cmulf(z2, W2);
        float2 u3 = cmulf(z3, W3);
        float2 u4 = cmulf(z4, W4);
        float2 u5 = cmulf(z5, W5);
        float2 u6 = cmulf(z6, W6);
        float2 u7 = cmulf(z7, W7);

        float2 t0 = cadd(u0, u4), t1 = csub(u0, u4);
        float2 t2 = cadd(u2, u6), t3 = csub(u2, u6);
        float2 E0 = cadd(t0, t2);
        float2 E1 = make_float2(t1.x + t3.y, t1.y - t3.x);
        float2 E2 = csub(t0, t2);
        float2 E3 = make_float2(t1.x - t3.y, t1.y + t3.x);
        float2 s0 = cadd(u1, u5), s1 = csub(u1, u5);
        float2 s2 = cadd(u3, u7), s3 = csub(u3, u7);
        float2 O0 = cadd(s0, s2);
        float2 O1 = make_float2(s1.x + s3.y, s1.y - s3.x);
        float2 O2 = csub(s0, s2);
        float2 O3 = make_float2(s1.x - s3.y, s1.y + s3.x);
        float2 Q1 = make_float2(RS * (O1.x + O1.y), RS * (O1.y - O1.x));
        float2 Q2 = make_float2(O2.y, -O2.x);
        float2 Q3 = make_float2(RS * (O3.y - O3.x), -RS * (O3.x + O3.y));

        const int ob = ((idx - r) << 3) + r;
        bout[F2PAD(ob)]         = cadd(E0, O0);
        bout[F2PAD(ob + m)]     = cadd(E1, Q1);
        bout[F2PAD(ob + 2 * m)] = cadd(E2, Q2);
        bout[F2PAD(ob + 3 * m)] = cadd(E3, Q3);
        bout[F2PAD(ob + 4 * m)] = csub(E0, O0);
        bout[F2PAD(ob + 5 * m)] = csub(E1, Q1);
        bout[F2PAD(ob + 6 * m)] = csub(E2, Q2);
        bout[F2PAD(ob + 7 * m)] = csub(E3, Q3);
        __syncthreads();
        float2* tmp = bin; bin = bout; bout = tmp;
    }

    {
        const int idx = tid;
        float2 W = tw[idx];

        float2 u0 = bin[F2PAD(idx)];
        float2 z1 = bin[F2PAD(idx + 512)];
        float2 z2 = bin[F2PAD(idx + 1024)];
        float2 z3 = bin[F2PAD(idx + 1536)];
        float2 z4 = bin[F2PAD(idx + 2048)];
        float2 z5 = bin[F2PAD(idx + 2560)];
        float2 z6 = bin[F2PAD(idx + 3072)];
        float2 z7 = bin[F2PAD(idx + 3584)];

        float2 W2 = cmulf(W, W);
        float2 W3 = cmulf(W2, W);
        float2 W4 = cmulf(W2, W2);
        float2 W5 = cmulf(W4, W);
        float2 W6 = cmulf(W4, W2);
        float2 W7 = cmulf(W4, W3);

        float2 u1 = cmulf(z1, W);
        float2 u2 = cmulf(z2, W2);
        float2 u3 = cmulf(z3, W3);
        float2 u4 = cmulf(z4, W4);
        float2 u5 = cmulf(z5, W5);
        float2 u6 = cmulf(z6, W6);
        float2 u7 = cmulf(z7, W7);

        float2 t0 = cadd(u0, u4), t1 = csub(u0, u4);
        float2 t2 = cadd(u2, u6), t3 = csub(u2, u6);
        float2 E0 = cadd(t0, t2);
        float2 E1 = make_float2(t1.x + t3.y, t1.y - t3.x);
        float2 E2 = csub(t0, t2);
        float2 E3 = make_float2(t1.x - t3.y, t1.y + t3.x);
        float2 s0 = cadd(u1, u5), s1 = csub(u1, u5);
        float2 s2 = cadd(u3, u7), s3 = csub(u3, u7);
        float2 O0 = cadd(s0, s2);
        float2 O1 = make_float2(s1.x + s3.y, s1.y - s3.x);
        float2 O2 = csub(s0, s2);
        float2 O3 = make_float2(s1.x - s3.y, s1.y + s3.x);
        float2 Q1 = make_float2(RS * (O1.x + O1.y), RS * (O1.y - O1.x));
        float2 Q2 = make_float2(O2.y, -O2.x);
        float2 Q3 = make_float2(RS * (O3.y - O3.x), -RS * (O3.x + O3.y));

        z[0] = cadd(E0, O0); z[1] = cadd(E1, Q1);
        z[2] = cadd(E2, Q2); z[3] = cadd(E3, Q3);
        z[4] = csub(E0, O0); z[5] = csub(E1, Q1);
        z[6] = csub(E2, Q2); z[7] = csub(E3, Q3);
#pragma unroll
        for (int q = 0; q < 8; q++)
            bout[F2PAD(idx + 512 * q)] = z[q];
    }
    __syncthreads();
    // bout holds Z_k natural order; thread tid holds z[q] = Z_{tid+512q}

    float psum = 0.f, wsum = 0.f;
#pragma unroll
    for (int q = 0; q < 8; q++) {
        const int k = tid + 512 * q;
        if (k > 0) {
            float2 zk = z[q];
            float2 zm = bout[F2PAD(M - k)];
            float Ax = 0.5f * (zk.x + zm.x), Ay = 0.5f * (zk.y - zm.y);
            float Bx = 0.5f * (zk.x - zm.x), By = 0.5f * (zk.y + zm.y);
            float s, c;
            __sincosf(-(float)CUDART_PI * (float)k / (float)M, &s, &c);
            float Xr = Ax + c * By + s * Bx;
            float Xi = Ay - c * Bx + s * By;
            float pw = Xr * Xr + Xi * Xi;
            psum += pw;
            wsum = fmaf((float)k, pw, wsum);
        }
    }
    if (tid == 0) {
        float xm = z[0].x - z[0].y;
        psum += xm * xm;
        wsum = fmaf((float)M, xm * xm, wsum);
    }

    float v0s = v0.x + v0.y;
    float v1s = v1.x + v1.y;

    const unsigned mask = 0xffffffffu;
#pragma unroll
    for (int o = 16; o > 0; o >>= 1) {
        psum += __shfl_down_sync(mask, psum, o);
        wsum += __shfl_down_sync(mask, wsum, o);
        v0s  += __shfl_down_sync(mask, v0s, o);
        v1s  += __shfl_down_sync(mask, v1s, o);
    }
    const int warp = tid >> 5, lane = tid & 31;
    if (lane == 0) {
        red[warp] = psum; red[16 + warp] = wsum;
        red[32 + warp] = v0s; red[48 + warp] = v1s;
    }
    __syncthreads();
    if (tid == 0) {
        double P = 0, Wm = 0, V0 = 0, V1 = 0;
        for (int i = 0; i < 16; i++) {
            P  += (double)red[i];
            Wm += (double)red[16 + i];
            V0 += (double)red[32 + i];
            V1 += (double)red[48 + i];
        }
        V0 += (double)fcb[e * 2];
        V1 += (double)fcb[e * 2 + 1];
        float f    = (float)(0.5 * Wm / P);
        float a    = 2.0f * sqrtf((float)P) / (float)T_LEN;
        float boff = (z[0].x + z[0].y) / (float)T_LEN;
        float p    = atan2f((float)V1, (float)V0) / TPI_F;
        pOut[be] = p; fOut[be] = f; aOut[be] = a; bOut[be] = boff;
    }
}

// ---------------------------------------------------------------------------
// Kernel D: sinusoid resynthesis + ANALYTIC deconv tree. (R9/R11 proven.)
// ---------------------------------------------------------------------------
__global__ __launch_bounds__(256) void sig_tree_kernel(
    const float* __restrict__ pArr, const float* __restrict__ fArr,
    const float* __restrict__ aArr, const float* __restrict__ bArr,
    const float* __restrict__ dW0, const float* __restrict__ db0,
    const float* __restrict__ dW1, const float* __restrict__ db1,
    const float* __restrict__ dW2, const float* __restrict__ db2,
    float* __restrict__ sig, float* __restrict__ outp)
{
    extern __shared__ float smd[];
    const int SW  = TD + 42;
    const int SPW = TD + 8;
    float2* ssig2 = (float2*)smd;
    float*  spart = (float*)(ssig2 + 4 * SW);
    float*  y0e   = spart + 4 * SPW;
    float*  y1e   = y0e + 4 * 36;

    __shared__ float sca[8], scf[8], scp[8], scb[8];
    __shared__ float2 rotv[8];
    __shared__ float sGr[8], sGi[8];
    __shared__ float sC;
    __shared__ ull sdw0p[4 * KS], sdw1p[2 * KS], sdw2p[KS];
    __shared__ float sdb0[4], sdb1[2], sdb2s;

    const int blk  = blockIdx.x;
    const int tile = blk & 7;
    const int b    = blk >> 3;
    const int t0   = tile * TD;
    const int tid  = threadIdx.x;
    const float inv = 2.0f / (float)(T_LEN - 1);

    if (tid < 8) {
        const int e = tid;
        float fv = fArr[b * 8 + e];
        float av = aArr[b * 8 + e];
        sca[e] = av; scf[e] = fv;
        scp[e] = pArr[b * 8 + e]; scb[e] = bArr[b * 8 + e];
        float S, C;
        sincospif(2.0f * fv * inv, &S, &C);
        rotv[e] = make_float2(C, S);

        float h0r = 0.f, h0i = 0.f, h1r = 0.f, h1i = 0.f, h2r = 0.f, h2i = 0.f;
        const int row1 = ((e >> 2) << 1) | ((e >> 1) & 1);
        const int row2 = e >> 2;
#pragma unroll
        for (int k = 0; k < KS; k++) {
            float ph = 2.0f * fv * (float)(k - 7) * inv;
            float ss, cc;
            sincospif(ph, &ss, &cc);
            float w0 = dW0[e * KS + k];
            float w1 = dW1[row1 * KS + k];
            float w2 = dW2[row2 * KS + k];
            h0r += w0 * cc; h0i += w0 * ss;
            h1r += w1 * cc; h1i += w1 * ss;
            h2r += w2 * cc; h2i += w2 * ss;
        }
        float g1r = h0r * h1r - h0i * h1i;
        float g1i = h0r * h1i + h0i * h1r;
        sGr[e] = av * (g1r * h2r - g1i * h2i);
        sGi[e] = av * (g1r * h2i + g1i * h2r);
    }
    if (tid == 8) {
        float S0[8], S1[4], S2[2];
        for (int e2 = 0; e2 < 8; e2++) {
            float s = 0.f;
            for (int k = 0; k < KS; k++) s += dW0[e2 * KS + k];
            S0[e2] = s;
        }
        for (int g = 0; g < 4; g++) {
            float s = 0.f;
            for (int k = 0; k < KS; k++) s += dW1[g * KS + k];
            S1[g] = s;
        }
        for (int q = 0; q < 2; q++) {
            float s = 0.f;
            for (int k = 0; k < KS; k++) s += dW2[q * KS + k];
            S2[q] = s;
        }
        float Cv = db2[0];
        for (int q = 0; q < 2; q++) Cv += S2[q] * db1[q];
        for (int g = 0; g < 4; g++) Cv += S2[g >> 1] * S1[g] * db0[g];
        for (int e2 = 0; e2 < 8; e2++)
            Cv += S2[e2 >> 2] * S1[e2 >> 1] * S0[e2] * bArr[b * 8 + e2];
        sC = Cv;
    }
    if (tid < 4 * KS) {
        int g = tid / KS, k = tid - g * KS;
        sdw0p[tid] = pk2(dW0[(2 * g) * KS + k], dW0[(2 * g + 1) * KS + k]);
    }
    if (tid < 2 * KS) {
        int g = tid / KS, k = tid - g * KS;
        sdw1p[tid] = pk2(dW1[(2 * g) * KS + k], dW1[(2 * g + 1) * KS + k]);
    }
    if (tid < KS) sdw2p[tid] = pk2(dW2[tid], dW2[KS + tid]);
    if (tid < 4) sdb0[tid] = db0[tid];
    if (tid < 2) sdb1[tid] = db1[tid];
    if (tid == 0) sdb2s = db2[0];
    __syncthreads();

    {
        const int pr  = tid >> 6;
        const int sub = tid & 63;
        const int j0  = sub * 17;
        const int ts  = t0 - 21 + j0;
        const int e0 = 2 * pr, e1 = 2 * pr + 1;
        const float arg0 = -1.0f + (float)ts * inv;
        float s0, c0, s1, c1;
        sincospif(2.0f * (scf[e0] * arg0 + scp[e0]), &s0, &c0);
        sincospif(2.0f * (scf[e1] * arg0 + scp[e1]), &s1, &c1);
        const float2 r0 = rotv[e0], r1 = rotv[e1];
        const float a0 = sca[e0], b0 = scb[e0];
        const float a1 = sca[e1], b1v = scb[e1];
        const float gr0 = sGr[e0], gi0 = sGi[e0];
        const float gr1 = sGr[e1], gi1 = sGi[e1];
        float* sprow = spart + pr * SPW;
#pragma unroll
        for (int jj = 0; jj < 17; jj++) {
            int j = j0 + jj;
            int t = ts + jj;
            if (j < SW) {
                bool ok = ((unsigned)t < (unsigned)T_LEN);
                float v0 = ok ? (a0 * s0 + b0)  : 0.f;
                float v1 = ok ? (a1 * s1 + b1v) : 0.f;
                ssig2[pr * SW + j] = make_float2(v0, v1);
                if (j >= 21 && j < 21 + TD)
                    sprow[j - 21] = gr0 * s0 + gi0 * c0 + gr1 * s1 + gi1 * c1;
            }
            float ns0 = s0 * r0.x + c0 * r0.y;
            c0 = c0 * r0.x - s0 * r0.y; s0 = ns0;
            float ns1 = s1 * r1.x + c1 * r1.y;
            c1 = c1 * r1.x - s1 * r1.y; s1 = ns1;
        }
    }
    __syncthreads();

    for (int i = tid; i < 8 * TD; i += 256) {
        int e = i >> 10, jj = i & (TD - 1);
        float2 v = ssig2[(e >> 1) * SW + 21 + jj];
        sig[((size_t)b * 8 + e) * T_LEN + t0 + jj] = (e & 1) ? v.y : v.x;
    }

    {
        const float Cv = sC;
        const bool left  = (tile == 0);
        const bool right = (tile == 7);
        float* orow = outp + (size_t)b * T_LEN + t0;
#pragma unroll
        for (int jj = tid; jj < TD; jj += 256) {
            bool skip = (left && jj < 21) || (right && jj >= TD - 21);
            if (!skip) {
                orow[jj] = spart[jj] + spart[SPW + jj] +
                           spart[2 * SPW + jj] + spart[3 * SPW + jj] + Cv;
            }
        }
    }

    {
        const bool left  = (tile == 0);
        const bool right = (tile == 7);
        const bool edge  = left || right;

        if (edge && tid < 140) {
            const int g = tid / 35, j = tid - g * 35;
            float acc = sdb0[g];
#pragma unroll
            for (int k = 0; k < KS; k++) {
                int tG = (left ? j : (T_LEN - 35 + j)) + k - 7;
                int slot = tG - t0 + 21;
                float2 w = unpk2(sdw0p[g * KS + k]);
                float2 sv = ssig2[g * SW + slot];
                acc += w.x * sv.x + w.y * sv.y;
            }
            y0e[g * 36 + j] = acc;
        }
        __syncthreads();

        if (edge && tid < 56) {
            const int g1 = tid / 28, j = tid - g1 * 28;
            float acc = sdb1[g1];
#pragma unroll
            for (int k = 0; k < KS; k++) {
                int idx; bool ok;
                if (left) { idx = j + k - 7; ok = (idx >= 0); }
                else      { idx = j + k;     ok = (idx < 35); }
                if (ok) {
                    float2 w = unpk2(sdw1p[g1 * KS + k]);
                    acc += w.x * y0e[(2 * g1) * 36 + idx]
                         + w.y * y0e[(2 * g1 + 1) * 36 + idx];
                }
            }
            y1e[g1 * 28 + j] = acc;
        }
        __syncthreads();

        if (edge && tid < 21) {
            float acc = sdb2s;
#pragma unroll
            for (int k = 0; k < KS; k++) {
                int idx; bool ok;
                if (left) { idx = tid + k - 7; ok = (idx >= 0); }
                else      { idx = tid + k;     ok = (idx < 28); }
                if (ok) {
                    float2 w = unpk2(sdw2p[k]);
                    acc += w.x * y1e[idx] + w.y * y1e[28 + idx];
                }
            }
            int tG = left ? tid : (T_LEN - 21 + tid);
            outp[(size_t)b * T_LEN + tG] = acc;
        }
    }
}

// ---------------------------------------------------------------------------
extern "C" void kernel_launch(void* const* d_in, const int* in_sizes, int n_in,
                              void* d_out, int out_size)
{
    const float* x   = (const float*)d_in[0];
    const float* W1  = (const float*)d_in[1];
    const float* b1  = (const float*)d_in[2];
    const float* W2  = (const float*)d_in[3];
    const float* b2  = (const float*)d_in[4];
    const float* fcW = (const float*)d_in[5];
    const float* fcb = (const float*)d_in[6];
    const float* dW0 = (const float*)d_in[7];
    const float* db0 = (const float*)d_in[8];
    const float* dW1 = (const float*)d_in[9];
    const float* db1 = (const float*)d_in[10];
    const float* dW2 = (const float*)d_in[11];
    const float* db2 = (const float*)d_in[12];

    float* out = (float*)d_out;
    float* outMain = out;                                        // (B, T)
    float* latent  = out + (size_t)B_SZ * T_LEN;                 // (B, E, T)
    float* sig     = latent + (size_t)B_SZ * E_CH * T_LEN;       // (B, E, T)
    float* pOut    = sig + (size_t)B_SZ * E_CH * T_LEN;          // (B, E, 1)
    float* fOut    = pOut + B_SZ * E_CH;
    float* aOut    = fOut + B_SZ * E_CH;
    float* bOut    = aOut + B_SZ * E_CH;

    const size_t smA = (size_t)8448 * sizeof(float) + (size_t)8704 * sizeof(ull);
    const size_t smB = (size_t)(4352 * 2 + 512) * sizeof(float2);   // 73728B
    const size_t smD = (size_t)(4 * (TD + 42)) * sizeof(float2)
                     + (size_t)(4 * (TD + 8) + 4 * 36 + 2 * 28) * sizeof(float);

    cudaFuncSetAttribute(latent_kernel,   cudaFuncAttributeMaxDynamicSharedMemorySize, (int)smA);
    cudaFuncSetAttribute(fft_kernel,      cudaFuncAttributeMaxDynamicSharedMemorySize, (int)smB);
    cudaFuncSetAttribute(sig_tree_kernel, cudaFuncAttributeMaxDynamicSharedMemorySize, (int)smD);

    latent_kernel<<<B_SZ * E_CH, 256, smA>>>(x, W1, b1, W2, b2, latent);
    fft_kernel<<<B_SZ * E_CH, 512, smB>>>(latent, fcW, fcb, pOut, fOut, aOut, bOut);
    sig_tree_kernel<<<B_SZ * (T_LEN / TD), 256, smD>>>(pOut, fOut, aOut, bOut,
                                                       dW0, db0, dW1, db1, dW2, db2,
                                                       sig, outMain);
}